// round 13
// baseline (speedup 1.0000x reference)
#include <cuda_runtime.h>
#include <cuda_fp8.h>
#include <math.h>

#define B 32
#define S 4096
#define H 16
#define KV_LORA 512
#define NOPE 128
#define ROPE 64
#define QKD 192
#define VD 128
#define QIN 1536
#define HID 2048
#define DKV 576
#define NQ (H*QKD)
#define SCALEF 0.07216878364870323f

#define CHUNK 256
#define NCHUNK (S/CHUNK)
#define ATILE 8
#define NBUF 4
#define KSQ 16
#define KSO 32
#define VS 8

typedef unsigned long long ull;

// ---------------- packed f32x2 helpers ----------------
__device__ __forceinline__ ull pk2(float x, float y){
  ull r; asm("mov.b64 %0, {%1, %2};" : "=l"(r) : "f"(x), "f"(y)); return r;
}
__device__ __forceinline__ float2 upk2(ull v){
  float2 r; asm("mov.b64 {%0, %1}, %2;" : "=f"(r.x), "=f"(r.y) : "l"(v)); return r;
}
__device__ __forceinline__ ull ffma2(ull a, ull b, ull c){
  ull d; asm("fma.rn.f32x2 %0, %1, %2, %3;" : "=l"(d) : "l"(a), "l"(b), "l"(c)); return d;
}
__device__ __forceinline__ ull fmul2(ull a, ull b){
  ull d; asm("mul.rn.f32x2 %0, %1, %2;" : "=l"(d) : "l"(a), "l"(b)); return d;
}

// ---------------- device scratch ----------------
static __device__ unsigned g_amax[2];
static __device__ float g_wscale[2];
static __device__ unsigned char g_WK8[H*KV_LORA*NOPE];
static __device__ unsigned char g_WV8[H*VD*KV_LORA];
static __device__ float g_qp_part[KSQ][B*NQ];
static __device__ float g_qn[B*H*NOPE];
static __device__ float g_qf[B*H*DKV];
static __device__ float g_newkv[B*DKV];
static __device__ float g_rope[B][32][2];
static __device__ float g_m[B*H*NCHUNK];
static __device__ float g_l[B*H*NCHUNK];
static __device__ float g_opart[(size_t)B*H*NCHUNK*KV_LORA];
static __device__ float g_o[B*H*KV_LORA];
static __device__ float g_t_part[VS][B*HID];
static __device__ float g_t[B*HID];
static __device__ float g_out_part[KSO][B*HID];

__global__ void k_amax(const float* __restrict__ WK, const float* __restrict__ WV){
  const int N4 = (H*KV_LORA*NOPE)/4;
  const float4* WK4 = (const float4*)WK;
  const float4* WV4 = (const float4*)WV;
  float m0 = 0.f, m1 = 0.f;
  for (int i = blockIdx.x*blockDim.x + threadIdx.x; i < N4; i += gridDim.x*blockDim.x){
    float4 a = WK4[i], b = WV4[i];
    m0 = fmaxf(m0, fmaxf(fmaxf(fabsf(a.x),fabsf(a.y)), fmaxf(fabsf(a.z),fabsf(a.w))));
    m1 = fmaxf(m1, fmaxf(fmaxf(fabsf(b.x),fabsf(b.y)), fmaxf(fabsf(b.z),fabsf(b.w))));
  }
  #pragma unroll
  for (int off = 16; off; off >>= 1){
    m0 = fmaxf(m0, __shfl_xor_sync(0xffffffffu, m0, off));
    m1 = fmaxf(m1, __shfl_xor_sync(0xffffffffu, m1, off));
  }
  __shared__ float s0[8], s1[8];
  int w = threadIdx.x >> 5;
  if ((threadIdx.x & 31) == 0){ s0[w] = m0; s1[w] = m1; }
  __syncthreads();
  if (threadIdx.x == 0){
    #pragma unroll
    for (int i = 1; i < 8; i++){ m0 = fmaxf(m0, s0[i]); m1 = fmaxf(m1, s1[i]); }
    atomicMax(&g_amax[0], __float_as_uint(m0));
    atomicMax(&g_amax[1], __float_as_uint(m1));
  }
}

// ---------------- rope trig table + new_kv rope ----------------
__global__ void k_rope(const float* __restrict__ kpe, const int* __restrict__ kv_lens){
  int b = blockIdx.x, i = threadIdx.x;
  int pos = kv_lens[b];
  double inv = exp(-((2.0*i)/64.0) * 9.210340371976184);
  double ang = (double)pos * inv;
  float cs = (float)cos(ang), sn = (float)sin(ang);
  g_rope[b][i][0] = cs;
  g_rope[b][i][1] = sn;
  float k1 = kpe[b*ROPE + i], k2 = kpe[b*ROPE + 32 + i];
  g_newkv[b*DKV + KV_LORA + i]      = k1*cs - k2*sn;
  g_newkv[b*DKV + KV_LORA + 32 + i] = k2*cs + k1*sn;
}

__device__ __forceinline__ unsigned q8(float v, float s){
  float x = fminf(fmaxf(v*s, -448.f), 448.f);
  return (unsigned)__nv_cvt_float_to_fp8(x, __NV_SATFINITE, __NV_E4M3);
}
__device__ __forceinline__ float fp8tf(unsigned char b){
  __half_raw h = __nv_cvt_fp8_to_halfraw((__nv_fp8_storage_t)b, __NV_E4M3);
  return __half2float(*(__half*)&h);
}

__global__ void k_quant(const float* __restrict__ WK, const float* __restrict__ WV){
  const int N16 = (H*KV_LORA*NOPE)/16;
  float aK = fmaxf(__uint_as_float(g_amax[0]), 1e-10f);
  float aV = fmaxf(__uint_as_float(g_amax[1]), 1e-10f);
  float sK = 448.f / aK, sV = 448.f / aV;
  if (blockIdx.x == 0 && threadIdx.x == 0){ g_wscale[0] = 1.f/sK; g_wscale[1] = 1.f/sV; }
  const float4* WK4 = (const float4*)WK;
  const float4* WV4 = (const float4*)WV;
  uint4* OK = (uint4*)g_WK8;
  uint4* OV = (uint4*)g_WV8;
  for (int i = blockIdx.x*blockDim.x + threadIdx.x; i < N16; i += gridDim.x*blockDim.x){
    uint4 ok, ov;
    unsigned* po = &ok.x;
    unsigned* pv = &ov.x;
    #pragma unroll
    for (int j = 0; j < 4; j++){
      float4 a = WK4[i*4 + j];
      po[j] = q8(a.x,sK) | (q8(a.y,sK)<<8) | (q8(a.z,sK)<<16) | (q8(a.w,sK)<<24);
      float4 b = WV4[i*4 + j];
      pv[j] = q8(b.x,sV) | (q8(b.y,sV)<<8) | (q8(b.z,sV)<<16) | (q8(b.w,sV)<<24);
    }
    OK[i] = ok; OV[i] = ov;
  }
}

// ---------------- qp = q @ Wq : 768 CTAs (64 cols x KSQ=16), 2 rows/thread ----------------
__global__ void __launch_bounds__(256) k_qp(const float* __restrict__ q,
                                            const float* __restrict__ Wq){
  __shared__ float xs[B][96];
  __shared__ __align__(16) float ws[2][32][64];
  int cb = blockIdx.x, ks = blockIdx.y;
  int tid = threadIdx.x;
  int tx = tid & 15, ty = tid >> 4;     // tx: 16 x float4 = 64 cols; ty: 16 groups x 2 rows
  int k0 = ks*96;
  #pragma unroll
  for (int it = 0; it < 3; it++){
    int idx = tid + it*256;
    int r = idx/24, c4 = idx - r*24;
    float4 v = ((const float4*)q)[r*(QIN/4) + (k0>>2) + c4];
    *(float4*)&xs[r][c4*4] = v;
  }
  auto loadw = [&](int c){
    int buf = c & 1;
    #pragma unroll
    for (int it = 0; it < 2; it++){
      int idx = tid + it*256;
      int r = idx >> 4, c4 = idx & 15;
      const float* src = Wq + (size_t)(k0 + c*32 + r)*NQ + cb*64 + c4*4;
      unsigned sa = (unsigned)__cvta_generic_to_shared(&ws[buf][r][c4*4]);
      asm volatile("cp.async.cg.shared.global [%0], [%1], 16;" :: "r"(sa), "l"(src));
    }
    asm volatile("cp.async.commit_group;" ::: "memory");
  };
  loadw(0);
  ull acc[2][2] = {};
  for (int c = 0; c < 3; c++){
    if (c < 2){
      loadw(c+1);
      asm volatile("cp.async.wait_group 1;" ::: "memory");
    } else {
      asm volatile("cp.async.wait_group 0;" ::: "memory");
    }
    __syncthreads();
    int buf = c & 1;
    #pragma unroll
    for (int k = 0; k < 32; k++){
      ulonglong2 w2 = ((const ulonglong2*)&ws[buf][k][0])[tx];
      #pragma unroll
      for (int i = 0; i < 2; i++){
        float xv = xs[ty*2+i][c*32+k];
        ull xv2 = pk2(xv, xv);
        acc[i][0] = ffma2(xv2, w2.x, acc[i][0]);
        acc[i][1] = ffma2(xv2, w2.y, acc[i][1]);
      }
    }
    __syncthreads();
  }
  float4* op = (float4*)g_qp_part[ks];
  #pragma unroll
  for (int i = 0; i < 2; i++){
    float2 a = upk2(acc[i][0]), b2 = upk2(acc[i][1]);
    op[(size_t)(ty*2+i)*(NQ/4) + cb*16 + tx] = make_float4(a.x,a.y,b2.x,b2.y);
  }
}

// ---------------- reduce qp partials + rope (table) + new_kv copy ----------------
__global__ void __launch_bounds__(256) k_qred(const float* __restrict__ kc){
  int b = blockIdx.x, cy = blockIdx.y;
  int tid = threadIdx.x;
  __shared__ float qs[256];
  int cbase = cy*256;
  int col = tid;
  {
    float s = 0.f;
    #pragma unroll
    for (int ks = 0; ks < KSQ; ks++) s += g_qp_part[ks][b*NQ + cbase + col];
    qs[col] = s;
  }
  __syncthreads();
  {
    int gc = cbase + col;
    int h = gc/192, off = gc - h*192;
    if (off < 128){
      g_qn[(b*H + h)*NOPE + off] = qs[col];
    } else if (off < 160){
      int i = off - 128;
      float cs = g_rope[b][i][0], sn = g_rope[b][i][1];
      float x1 = qs[col], x2 = qs[col+32];
      float* qf = g_qf + (size_t)(b*H + h)*DKV;
      qf[KV_LORA + i]      = (x1*cs - x2*sn)*SCALEF;
      qf[KV_LORA + 32 + i] = (x2*cs + x1*sn)*SCALEF;
    }
  }
  if (cy < 2){
    int c = cy*256 + tid;
    g_newkv[b*DKV + c] = kc[b*KV_LORA + c];
  }
}

// ---------------- ql_nope = q_nope @ W_Kd^T (fp8 weights) ----------------
__global__ void __launch_bounds__(256) k_qk(){
  int h = blockIdx.y, c0 = blockIdx.x*64;
  int tid = threadIdx.x;
  int cc = tid & 63, rg = tid >> 6;
  __shared__ float qn_s[B][NOPE];
  __shared__ float ws[64][33];
  float invK = g_wscale[0];
  for (int idx = tid; idx < B*(NOPE/4); idx += 256){
    int r = idx >> 5, d4 = idx & 31;
    float4 v = ((const float4*)(g_qn + (size_t)(r*H + h)*NOPE))[d4];
    qn_s[r][d4*4+0]=v.x; qn_s[r][d4*4+1]=v.y; qn_s[r][d4*4+2]=v.z; qn_s[r][d4*4+3]=v.w;
  }
  float acc[8];
  #pragma unroll
  for (int i = 0; i < 8; i++) acc[i] = 0.f;
  for (int db = 0; db < NOPE; db += 32){
    __syncthreads();
    #pragma unroll
    for (int it = 0; it < 2; it++){
      int idx = tid + it*256;
      int c = idx >> 3, d4 = (idx & 7)*4;
      const unsigned char* p = g_WK8 + (size_t)(h*KV_LORA + c0 + c)*NOPE + db + d4;
      uchar4 v = *(const uchar4*)p;
      ws[c][d4+0]=fp8tf(v.x); ws[c][d4+1]=fp8tf(v.y); ws[c][d4+2]=fp8tf(v.z); ws[c][d4+3]=fp8tf(v.w);
    }
    __syncthreads();
    #pragma unroll
    for (int d = 0; d < 32; d++){
      float w = ws[cc][d];
      #pragma unroll
      for (int r = 0; r < 8; r++)
        acc[r] += qn_s[rg*8 + r][db + d]*w;
    }
  }
  float sc = SCALEF*invK;
  #pragma unroll
  for (int r = 0; r < 8; r++){
    int b = rg*8 + r;
    g_qf[(size_t)(b*H + h)*DKV + c0 + cc] = acc[r]*sc;
  }
}

// ---------------- flash attention (unchanged, measured best) ----------------
__global__ void __launch_bounds__(128, 2) k_attn(const float* __restrict__ kv_cache,
                                                 const int* __restrict__ kv_lens){
  extern __shared__ float kvs[];
  __shared__ float ps[4][32];
  int chunk = blockIdx.x, b = blockIdx.y;
  int len = kv_lens[b];
  int s_begin = chunk*CHUNK;
  if (s_begin > len) return;
  int s_end = min(s_begin + CHUNK, len + 1);
  int T = (s_end - s_begin + ATILE - 1)/ATILE;

  int tid = threadIdx.x;
  int warp = tid >> 5, lane = tid & 31;
  int myh = lane >> 3, myr = lane & 7;

  ulonglong2 q4[4][4]; ull qt[4];
  #pragma unroll
  for (int h = 0; h < 4; h++){
    const float* qf = g_qf + (size_t)(b*H + warp*4 + h)*DKV;
    #pragma unroll
    for (int j = 0; j < 4; j++) q4[h][j] = ((const ulonglong2*)qf)[j*32 + lane];
    qt[h] = ((const ull*)qf)[256 + lane];
  }

  ull acc[4][8];
  #pragma unroll
  for (int h = 0; h < 4; h++)
    #pragma unroll
    for (int j = 0; j < 8; j++) acc[h][j] = 0ull;
  float mh = -1e30f, lh = 0.f;

  auto load_tile = [&](int t){
    int buf = t & (NBUF-1);
    int t0 = s_begin + t*ATILE;
    int rows = min(ATILE, s_end - t0);
    float* dst = kvs + buf*(ATILE*DKV);
    for (int idx = tid; idx < rows*144; idx += 128){
      int r = idx/144, c4 = idx - r*144;
      int s = t0 + r;
      const float* src = (s == len) ? (g_newkv + b*DKV + c4*4)
                                    : (kv_cache + ((size_t)b*S + s)*DKV + c4*4);
      unsigned sa = (unsigned)__cvta_generic_to_shared(dst + r*DKV + c4*4);
      asm volatile("cp.async.cg.shared.global [%0], [%1], 16;" :: "r"(sa), "l"(src));
    }
    if (rows < ATILE)
      for (int idx = tid + rows*144; idx < ATILE*144; idx += 128){
        int r = idx/144, c4 = idx - r*144;
        *(float4*)(dst + r*DKV + c4*4) = make_float4(0.f,0.f,0.f,0.f);
      }
    asm volatile("cp.async.commit_group;" ::: "memory");
  };

  load_tile(0);
  if (T > 1) load_tile(1);
  if (T > 2) load_tile(2);
  for (int t = 0; t < T; t++){
    int rem = T - 1 - t;
    if (rem >= 2)      asm volatile("cp.async.wait_group 2;" ::: "memory");
    else if (rem == 1) asm volatile("cp.async.wait_group 1;" ::: "memory");
    else               asm volatile("cp.async.wait_group 0;" ::: "memory");
    __syncthreads();
    if (t + 3 < T) load_tile(t+3);

    const float* kb = kvs + (t & (NBUF-1))*(ATILE*DKV);
    int t0 = s_begin + t*ATILE;

    float x[32];
    #pragma unroll
    for (int r = 0; r < 8; r++){
      const ulonglong2* row4 = (const ulonglong2*)(kb + r*DKV);
      ull s0=0, s1=0, s2=0, s3=0;
      #pragma unroll
      for (int j = 0; j < 4; j++){
        ulonglong2 kv = row4[j*32 + lane];
        s0 = ffma2(q4[0][j].x, kv.x, s0); s0 = ffma2(q4[0][j].y, kv.y, s0);
        s1 = ffma2(q4[1][j].x, kv.x, s1); s1 = ffma2(q4[1][j].y, kv.y, s1);
        s2 = ffma2(q4[2][j].x, kv.x, s2); s2 = ffma2(q4[2][j].y, kv.y, s2);
        s3 = ffma2(q4[3][j].x, kv.x, s3); s3 = ffma2(q4[3][j].y, kv.y, s3);
      }
      ull kt = ((const ull*)(kb + r*DKV))[256 + lane];
      s0 = ffma2(qt[0], kt, s0);
      s1 = ffma2(qt[1], kt, s1);
      s2 = ffma2(qt[2], kt, s2);
      s3 = ffma2(qt[3], kt, s3);
      float2 v0=upk2(s0), v1=upk2(s1), v2=upk2(s2), v3=upk2(s3);
      x[0*8+r] = v0.x+v0.y; x[1*8+r] = v1.x+v1.y;
      x[2*8+r] = v2.x+v2.y; x[3*8+r] = v3.x+v3.y;
    }
    #pragma unroll
    for (int off = 16; off >= 1; off >>= 1){
      bool hi = (lane & off) != 0;
      #pragma unroll
      for (int i = 0; i < off; i++){
        float send = hi ? x[i] : x[i+off];
        float recv = __shfl_xor_sync(0xffffffffu, send, off);
        x[i] = (hi ? x[i+off] : x[i]) + recv;
      }
    }
    bool valid = (t0 + myr) < s_end;
    float sc = valid ? x[0] : -1e30f;

    float tm = sc;
    tm = fmaxf(tm, __shfl_xor_sync(0xffffffffu, tm, 4));
    tm = fmaxf(tm, __shfl_xor_sync(0xffffffffu, tm, 2));
    tm = fmaxf(tm, __shfl_xor_sync(0xffffffffu, tm, 1));
    float nm = fmaxf(mh, tm);
    float cf = __expf(mh - nm);
    mh = nm;
    float p = valid ? __expf(sc - nm) : 0.f;
    float sp = p;
    sp += __shfl_xor_sync(0xffffffffu, sp, 4);
    sp += __shfl_xor_sync(0xffffffffu, sp, 2);
    sp += __shfl_xor_sync(0xffffffffu, sp, 1);
    lh = lh*cf + sp;

    ps[warp][myr*4 + myh] = p;
    if (!__all_sync(0xffffffffu, cf == 1.0f)){
      #pragma unroll
      for (int h = 0; h < 4; h++){
        float cfh = __shfl_sync(0xffffffffu, cf, h*8);
        ull c2 = pk2(cfh, cfh);
        #pragma unroll
        for (int j = 0; j < 8; j++) acc[h][j] = fmul2(acc[h][j], c2);
      }
    }
    __syncwarp();

    #pragma unroll
    for (int r = 0; r < 8; r++){
      float4 pv = *(const float4*)&ps[warp][r*4];
      ull pp0 = pk2(pv.x,pv.x), pp1 = pk2(pv.y,pv.y), pp2 = pk2(pv.z,pv.z), pp3 = pk2(pv.w,pv.w);
      const ulonglong2* row4 = (const ulonglong2*)(kb + r*DKV);
      #pragma unroll
      for (int j = 0; j < 4; j++){
        ulonglong2 kv = row4[j*32 + lane];
        acc[0][2*j]   = ffma2(pp0, kv.x, acc[0][2*j]);
        acc[0][2*j+1] = ffma2(pp0, kv.y, acc[0][2*j+1]);
        acc[1][2*j]   = ffma2(pp1, kv.x, acc[1][2*j]);
        acc[1][2*j+1] = ffma2(pp1, kv.y, acc[1][2*j+1]);
        acc[2][2*j]   = ffma2(pp2, kv.x, acc[2][2*j]);
        acc[2][2*j+1] = ffma2(pp2, kv.y, acc[2][2*j+1]);
        acc[3][2*j]   = ffma2(pp3, kv.x, acc[3][2*j]);
        acc[3][2*j+1] = ffma2(pp3, kv.y, acc[3][2*j+1]);
      }
    }
  }

  #pragma unroll
  for (int h = 0; h < 4; h++){
    int basep = (b*H + warp*4 + h)*NCHUNK + chunk;
    if (lane == h*8){ g_m[basep] = mh; g_l[basep] = lh; }
    ull* op = (ull*)g_opart + (size_t)basep*256;
    #pragma unroll
    for (int j = 0; j < 4; j++){
      op[j*64 + lane*2]     = acc[h][2*j];
      op[j*64 + lane*2 + 1] = acc[h][2*j+1];
    }
  }
}

// ---------------- combine split-softmax partials (weights hoisted) ----------------
__global__ void __launch_bounds__(128) k_comb(const int* __restrict__ kv_lens){
  int h = blockIdx.x, b = blockIdx.y;
  int tid = threadIdx.x;
  int len = kv_lens[b];
  int cmax = min(NCHUNK - 1, len >> 8);
  int base = (b*H + h)*NCHUNK;
  float mstar = -1e30f;
  for (int c = 0; c <= cmax; c++) mstar = fmaxf(mstar, g_m[base + c]);
  float ecf[NCHUNK];
  float lstar = 0.f;
  for (int c = 0; c <= cmax; c++){
    float e = expf(g_m[base + c] - mstar);
    ecf[c] = e;
    lstar += e * g_l[base + c];
  }
  float inv_l = 1.f / lstar;
  #pragma unroll
  for (int j = 0; j < KV_LORA/128; j++){
    int d = tid + j*128;
    float s = 0.f;
    for (int c = 0; c <= cmax; c++)
      s += ecf[c] * g_opart[(size_t)(base + c)*KV_LORA + d];
    g_o[(size_t)(b*H + h)*KV_LORA + d] = s * inv_l;
  }
}

// ---------------- t = o @ W_Vd^T (fp8 weights) ----------------
__global__ void __launch_bounds__(256) k_v(){
  int cs = blockIdx.x, h = blockIdx.y;
  int tid = threadIdx.x;
  int vv = tid & 127, rg = tid >> 7;
  __shared__ float ws[128][33];
  __shared__ float os[B][32];
  float invV = g_wscale[1];
  float acc[16];
  #pragma unroll
  for (int i = 0; i < 16; i++) acc[i] = 0.f;
  for (int cbk = 0; cbk < 64; cbk += 32){
    int c0 = cs*64 + cbk;
    __syncthreads();
    #pragma unroll
    for (int it = 0; it < 4; it++){
      int idx = tid + it*256;
      int v = idx >> 3, d4 = (idx & 7)*4;
      const unsigned char* p = g_WV8 + (size_t)(h*VD + v)*KV_LORA + c0 + d4;
      uchar4 u = *(const uchar4*)p;
      ws[v][d4+0]=fp8tf(u.x); ws[v][d4+1]=fp8tf(u.y); ws[v][d4+2]=fp8tf(u.z); ws[v][d4+3]=fp8tf(u.w);
    }
    for (int idx = tid; idx < B*8; idx += 256){
      int r = idx >> 3, d4 = (idx & 7)*4;
      float4 v = *(const float4*)(g_o + (size_t)(r*H + h)*KV_LORA + c0 + d4);
      os[r][d4+0]=v.x; os[r][d4+1]=v.y; os[r][d4+2]=v.z; os[r][d4+3]=v.w;
    }
    __syncthreads();
    #pragma unroll
    for (int d = 0; d < 32; d++){
      float w = ws[vv][d];
      #pragma unroll
      for (int r = 0; r < 16; r++)
        acc[r] += os[rg*16 + r][d]*w;
    }
  }
  #pragma unroll
  for (int r = 0; r < 16; r++){
    int b = rg*16 + r;
    g_t_part[cs][b*HID + h*VD + vv] = acc[r]*invV;
  }
}

__global__ void k_tred(){
  int i = blockIdx.x*blockDim.x + threadIdx.x;
  if (i < B*HID){
    float s = 0.f;
    #pragma unroll
    for (int p = 0; p < VS; p++) s += g_t_part[p][i];
    g_t[i] = s;
  }
}

// ---------------- out = t @ Wo : 1024 CTAs (64 cols x KSO=32), 2 rows/thread ----------------
__global__ void __launch_bounds__(256) k_out(const float* __restrict__ Wo){
  __shared__ float xs[B][64];
  __shared__ __align__(16) float ws[2][32][64];
  int cb = blockIdx.x, ks = blockIdx.y;
  int tid = threadIdx.x;
  int tx = tid & 15, ty = tid >> 4;
  int k0 = ks*64;
  #pragma unroll
  for (int it = 0; it < 2; it++){
    int idx = tid + it*256;
    int r = idx >> 4, c4 = idx & 15;
    float4 v = ((const float4*)g_t)[r*(HID/4) + (k0>>2) + c4];
    *(float4*)&xs[r][c4*4] = v;
  }
  auto loadw = [&](int c){
    int buf = c & 1;
    #pragma unroll
    for (int it = 0; it < 2; it++){
      int idx = tid + it*256;
      int r = idx >> 4, c4 = idx & 15;
      const float* src = Wo + (size_t)(k0 + c*32 + r)*HID + cb*64 + c4*4;
      unsigned sa = (unsigned)__cvta_generic_to_shared(&ws[buf][r][c4*4]);
      asm volatile("cp.async.cg.shared.global [%0], [%1], 16;" :: "r"(sa), "l"(src));
    }
    asm volatile("cp.async.commit_group;" ::: "memory");
  };
  loadw(0);
  ull acc[2][2] = {};
  for (int c = 0; c < 2; c++){
    if (c < 1){
      loadw(1);
      asm volatile("cp.async.wait_group 1;" ::: "memory");
    } else {
      asm volatile("cp.async.wait_group 0;" ::: "memory");
    }
    __syncthreads();
    int buf = c & 1;
    #pragma unroll
    for (int k = 0; k < 32; k++){
      ulonglong2 w2 = ((const ulonglong2*)&ws[buf][k][0])[tx];
      #pragma unroll
      for (int i = 0; i < 2; i++){
        float xv = xs[ty*2+i][c*32+k];
        ull xv2 = pk2(xv, xv);
        acc[i][0] = ffma2(xv2, w2.x, acc[i][0]);
        acc[i][1] = ffma2(xv2, w2.y, acc[i][1]);
      }
    }
    __syncthreads();
  }
  float4* op = (float4*)g_out_part[ks];
  #pragma unroll
  for (int i = 0; i < 2; i++){
    float2 a = upk2(acc[i][0]), b2 = upk2(acc[i][1]);
    op[(size_t)(ty*2+i)*(HID/4) + cb*16 + tx] = make_float4(a.x,a.y,b2.x,b2.y);
  }
}

__global__ void k_sum(float* __restrict__ out){
  int i = blockIdx.x*blockDim.x + threadIdx.x;
  if (i < B*HID){
    float s = 0.f;
    #pragma unroll
    for (int ks = 0; ks < KSO; ks++) s += g_out_part[ks][i];
    out[i] = s;
  }
}

extern "C" void kernel_launch(void* const* d_in, const int* in_sizes, int n_in,
                              void* d_out, int out_size){
  const float* q   = (const float*)d_in[0];
  const float* kc  = (const float*)d_in[1];
  const float* kpe = (const float*)d_in[2];
  const float* kvc = (const float*)d_in[3];
  const float* Wq  = (const float*)d_in[4];
  const float* WK  = (const float*)d_in[5];
  const float* WV  = (const float*)d_in[6];
  const float* Wo  = (const float*)d_in[7];
  const int*  lens = (const int*)d_in[8];

  cudaFuncSetAttribute(k_attn, cudaFuncAttributeMaxDynamicSharedMemorySize, NBUF*ATILE*DKV*4);

  k_rope<<<B, 32>>>(kpe, lens);
  k_amax<<<256, 256>>>(WK, WV);
  k_quant<<<512, 256>>>(WK, WV);
  k_qp<<<dim3(NQ/64, KSQ), 256>>>(q, Wq);
  k_qred<<<dim3(B, NQ/256), 256>>>(kc);
  k_qk<<<dim3(KV_LORA/64, H), 256>>>();
  k_attn<<<dim3(NCHUNK, B), 128, NBUF*ATILE*DKV*4>>>(kvc, lens);
  k_comb<<<dim3(H, B), 128>>>(lens);
  k_v<<<dim3(VS, H), 256>>>();
  k_tred<<<256, 256>>>();
  k_out<<<dim3(HID/64, KSO), 256>>>(Wo);
  k_sum<<<256, 256>>>((float*)d_out);
}

// round 14
// speedup vs baseline: 1.0518x; 1.0518x over previous
#include <cuda_runtime.h>
#include <cuda_fp8.h>
#include <math.h>

#define B 32
#define S 4096
#define H 16
#define KV_LORA 512
#define NOPE 128
#define ROPE 64
#define QKD 192
#define VD 128
#define QIN 1536
#define HID 2048
#define DKV 576
#define NQ (H*QKD)
#define SCALEF 0.07216878364870323f

#define CHUNK 256
#define NCHUNK (S/CHUNK)
#define ATILE 8
#define NBUF 4
#define KSQ 16
#define KSO 16
#define VS 8

typedef unsigned long long ull;

// ---------------- packed f32x2 helpers ----------------
__device__ __forceinline__ ull pk2(float x, float y){
  ull r; asm("mov.b64 %0, {%1, %2};" : "=l"(r) : "f"(x), "f"(y)); return r;
}
__device__ __forceinline__ float2 upk2(ull v){
  float2 r; asm("mov.b64 {%0, %1}, %2;" : "=f"(r.x), "=f"(r.y) : "l"(v)); return r;
}
__device__ __forceinline__ ull ffma2(ull a, ull b, ull c){
  ull d; asm("fma.rn.f32x2 %0, %1, %2, %3;" : "=l"(d) : "l"(a), "l"(b), "l"(c)); return d;
}
__device__ __forceinline__ ull fmul2(ull a, ull b){
  ull d; asm("mul.rn.f32x2 %0, %1, %2;" : "=l"(d) : "l"(a), "l"(b)); return d;
}

// ---------------- device scratch ----------------
static __device__ unsigned g_amax[2];
static __device__ float g_wscale[2];
static __device__ unsigned char g_WK8[H*KV_LORA*NOPE];
static __device__ unsigned char g_WV8[H*VD*KV_LORA];
static __device__ float g_qp_part[KSQ][B*NQ];
static __device__ float g_qn[B*H*NOPE];
static __device__ float g_qf[B*H*DKV];
static __device__ float g_newkv[B*DKV];
static __device__ float g_rope[B][32][2];
static __device__ float g_m[B*H*NCHUNK];
static __device__ float g_l[B*H*NCHUNK];
static __device__ float g_opart[(size_t)B*H*NCHUNK*KV_LORA];
static __device__ float g_o[B*H*KV_LORA];
static __device__ float g_t_part[VS][B*HID];
static __device__ float g_t[B*HID];
static __device__ float g_out_part[KSO][B*HID];

__global__ void k_amax(const float* __restrict__ WK, const float* __restrict__ WV){
  const int N4 = (H*KV_LORA*NOPE)/4;
  const float4* WK4 = (const float4*)WK;
  const float4* WV4 = (const float4*)WV;
  float m0 = 0.f, m1 = 0.f;
  for (int i = blockIdx.x*blockDim.x + threadIdx.x; i < N4; i += gridDim.x*blockDim.x){
    float4 a = WK4[i], b = WV4[i];
    m0 = fmaxf(m0, fmaxf(fmaxf(fabsf(a.x),fabsf(a.y)), fmaxf(fabsf(a.z),fabsf(a.w))));
    m1 = fmaxf(m1, fmaxf(fmaxf(fabsf(b.x),fabsf(b.y)), fmaxf(fabsf(b.z),fabsf(b.w))));
  }
  #pragma unroll
  for (int off = 16; off; off >>= 1){
    m0 = fmaxf(m0, __shfl_xor_sync(0xffffffffu, m0, off));
    m1 = fmaxf(m1, __shfl_xor_sync(0xffffffffu, m1, off));
  }
  __shared__ float s0[8], s1[8];
  int w = threadIdx.x >> 5;
  if ((threadIdx.x & 31) == 0){ s0[w] = m0; s1[w] = m1; }
  __syncthreads();
  if (threadIdx.x == 0){
    #pragma unroll
    for (int i = 1; i < 8; i++){ m0 = fmaxf(m0, s0[i]); m1 = fmaxf(m1, s1[i]); }
    atomicMax(&g_amax[0], __float_as_uint(m0));
    atomicMax(&g_amax[1], __float_as_uint(m1));
  }
}

// ---------------- rope trig table + new_kv rope ----------------
__global__ void k_rope(const float* __restrict__ kpe, const int* __restrict__ kv_lens){
  int b = blockIdx.x, i = threadIdx.x;
  int pos = kv_lens[b];
  double inv = exp(-((2.0*i)/64.0) * 9.210340371976184);
  double ang = (double)pos * inv;
  float cs = (float)cos(ang), sn = (float)sin(ang);
  g_rope[b][i][0] = cs;
  g_rope[b][i][1] = sn;
  float k1 = kpe[b*ROPE + i], k2 = kpe[b*ROPE + 32 + i];
  g_newkv[b*DKV + KV_LORA + i]      = k1*cs - k2*sn;
  g_newkv[b*DKV + KV_LORA + 32 + i] = k2*cs + k1*sn;
}

__device__ __forceinline__ unsigned q8(float v, float s){
  float x = fminf(fmaxf(v*s, -448.f), 448.f);
  return (unsigned)__nv_cvt_float_to_fp8(x, __NV_SATFINITE, __NV_E4M3);
}
__device__ __forceinline__ float fp8tf(unsigned char b){
  __half_raw h = __nv_cvt_fp8_to_halfraw((__nv_fp8_storage_t)b, __NV_E4M3);
  return __half2float(*(__half*)&h);
}

__global__ void k_quant(const float* __restrict__ WK, const float* __restrict__ WV){
  const int N16 = (H*KV_LORA*NOPE)/16;
  float aK = fmaxf(__uint_as_float(g_amax[0]), 1e-10f);
  float aV = fmaxf(__uint_as_float(g_amax[1]), 1e-10f);
  float sK = 448.f / aK, sV = 448.f / aV;
  if (blockIdx.x == 0 && threadIdx.x == 0){ g_wscale[0] = 1.f/sK; g_wscale[1] = 1.f/sV; }
  const float4* WK4 = (const float4*)WK;
  const float4* WV4 = (const float4*)WV;
  uint4* OK = (uint4*)g_WK8;
  uint4* OV = (uint4*)g_WV8;
  for (int i = blockIdx.x*blockDim.x + threadIdx.x; i < N16; i += gridDim.x*blockDim.x){
    uint4 ok, ov;
    unsigned* po = &ok.x;
    unsigned* pv = &ov.x;
    #pragma unroll
    for (int j = 0; j < 4; j++){
      float4 a = WK4[i*4 + j];
      po[j] = q8(a.x,sK) | (q8(a.y,sK)<<8) | (q8(a.z,sK)<<16) | (q8(a.w,sK)<<24);
      float4 b = WV4[i*4 + j];
      pv[j] = q8(b.x,sV) | (q8(b.y,sV)<<8) | (q8(b.z,sV)<<16) | (q8(b.w,sV)<<24);
    }
    OK[i] = ok; OV[i] = ov;
  }
}

// ---------------- qp = q @ Wq : KSQ=16, 4 rows/thread, 128 cols/CTA, TRANSPOSED xs ----------------
__global__ void __launch_bounds__(256) k_qp(const float* __restrict__ q,
                                            const float* __restrict__ Wq){
  __shared__ __align__(16) float xst[96][36];   // [k][row], row-dim padded: 36*4=144B (16B aligned rows)
  __shared__ __align__(16) float ws[2][32][128];
  int cb = blockIdx.x, ks = blockIdx.y;
  int tid = threadIdx.x;
  int tx = tid & 31, ty = tid >> 5;     // tx: 32 x float4 = 128 cols; ty: 8 groups x 4 rows
  int k0 = ks*96;
  #pragma unroll
  for (int it = 0; it < 3; it++){
    int idx = tid + it*256;
    int r = idx/24, c4 = idx - r*24;
    float4 v = ((const float4*)q)[r*(QIN/4) + (k0>>2) + c4];
    xst[c4*4+0][r]=v.x; xst[c4*4+1][r]=v.y; xst[c4*4+2][r]=v.z; xst[c4*4+3][r]=v.w;
  }
  auto loadw = [&](int c){
    int buf = c & 1;
    #pragma unroll
    for (int it = 0; it < 4; it++){
      int idx = tid + it*256;
      int r = idx >> 5, c4 = idx & 31;
      const float* src = Wq + (size_t)(k0 + c*32 + r)*NQ + cb*128 + c4*4;
      unsigned sa = (unsigned)__cvta_generic_to_shared(&ws[buf][r][c4*4]);
      asm volatile("cp.async.cg.shared.global [%0], [%1], 16;" :: "r"(sa), "l"(src));
    }
    asm volatile("cp.async.commit_group;" ::: "memory");
  };
  loadw(0);
  ull acc[4][2] = {};
  for (int c = 0; c < 3; c++){
    if (c < 2){
      loadw(c+1);
      asm volatile("cp.async.wait_group 1;" ::: "memory");
    } else {
      asm volatile("cp.async.wait_group 0;" ::: "memory");
    }
    __syncthreads();
    int buf = c & 1;
    #pragma unroll
    for (int k = 0; k < 32; k++){
      ulonglong2 w2 = ((const ulonglong2*)&ws[buf][k][0])[tx];
      float4 xv = *(const float4*)&xst[c*32+k][ty*4];   // one broadcast LDS.128
      ull x0 = pk2(xv.x,xv.x), x1 = pk2(xv.y,xv.y), x2 = pk2(xv.z,xv.z), x3 = pk2(xv.w,xv.w);
      acc[0][0] = ffma2(x0, w2.x, acc[0][0]); acc[0][1] = ffma2(x0, w2.y, acc[0][1]);
      acc[1][0] = ffma2(x1, w2.x, acc[1][0]); acc[1][1] = ffma2(x1, w2.y, acc[1][1]);
      acc[2][0] = ffma2(x2, w2.x, acc[2][0]); acc[2][1] = ffma2(x2, w2.y, acc[2][1]);
      acc[3][0] = ffma2(x3, w2.x, acc[3][0]); acc[3][1] = ffma2(x3, w2.y, acc[3][1]);
    }
    __syncthreads();
  }
  float4* op = (float4*)g_qp_part[ks];
  #pragma unroll
  for (int i = 0; i < 4; i++){
    float2 a = upk2(acc[i][0]), b2 = upk2(acc[i][1]);
    op[(size_t)(ty*4+i)*(NQ/4) + cb*32 + tx] = make_float4(a.x,a.y,b2.x,b2.y);
  }
}

// ---------------- reduce qp partials + rope (table) + new_kv copy ----------------
__global__ void __launch_bounds__(256) k_qred(const float* __restrict__ kc){
  int b = blockIdx.x, cy = blockIdx.y;
  int tid = threadIdx.x;
  __shared__ float qs[256];
  int cbase = cy*256;
  int col = tid;
  {
    float s = 0.f;
    #pragma unroll
    for (int ks = 0; ks < KSQ; ks++) s += g_qp_part[ks][b*NQ + cbase + col];
    qs[col] = s;
  }
  __syncthreads();
  {
    int gc = cbase + col;
    int h = gc/192, off = gc - h*192;
    if (off < 128){
      g_qn[(b*H + h)*NOPE + off] = qs[col];
    } else if (off < 160){
      int i = off - 128;
      float cs = g_rope[b][i][0], sn = g_rope[b][i][1];
      float x1 = qs[col], x2 = qs[col+32];
      float* qf = g_qf + (size_t)(b*H + h)*DKV;
      qf[KV_LORA + i]      = (x1*cs - x2*sn)*SCALEF;
      qf[KV_LORA + 32 + i] = (x2*cs + x1*sn)*SCALEF;
    }
  }
  if (cy < 2){
    int c = cy*256 + tid;
    g_newkv[b*DKV + c] = kc[b*KV_LORA + c];
  }
}

// ---------------- ql_nope = q_nope @ W_Kd^T (fp8 weights) ----------------
__global__ void __launch_bounds__(256) k_qk(){
  int h = blockIdx.y, c0 = blockIdx.x*64;
  int tid = threadIdx.x;
  int cc = tid & 63, rg = tid >> 6;
  __shared__ float qn_s[B][NOPE];
  __shared__ float ws[64][33];
  float invK = g_wscale[0];
  for (int idx = tid; idx < B*(NOPE/4); idx += 256){
    int r = idx >> 5, d4 = idx & 31;
    float4 v = ((const float4*)(g_qn + (size_t)(r*H + h)*NOPE))[d4];
    qn_s[r][d4*4+0]=v.x; qn_s[r][d4*4+1]=v.y; qn_s[r][d4*4+2]=v.z; qn_s[r][d4*4+3]=v.w;
  }
  float acc[8];
  #pragma unroll
  for (int i = 0; i < 8; i++) acc[i] = 0.f;
  for (int db = 0; db < NOPE; db += 32){
    __syncthreads();
    #pragma unroll
    for (int it = 0; it < 2; it++){
      int idx = tid + it*256;
      int c = idx >> 3, d4 = (idx & 7)*4;
      const unsigned char* p = g_WK8 + (size_t)(h*KV_LORA + c0 + c)*NOPE + db + d4;
      uchar4 v = *(const uchar4*)p;
      ws[c][d4+0]=fp8tf(v.x); ws[c][d4+1]=fp8tf(v.y); ws[c][d4+2]=fp8tf(v.z); ws[c][d4+3]=fp8tf(v.w);
    }
    __syncthreads();
    #pragma unroll
    for (int d = 0; d < 32; d++){
      float w = ws[cc][d];
      #pragma unroll
      for (int r = 0; r < 8; r++)
        acc[r] += qn_s[rg*8 + r][db + d]*w;
    }
  }
  float sc = SCALEF*invK;
  #pragma unroll
  for (int r = 0; r < 8; r++){
    int b = rg*8 + r;
    g_qf[(size_t)(b*H + h)*DKV + c0 + cc] = acc[r]*sc;
  }
}

// ---------------- flash attention (unchanged, measured best) ----------------
__global__ void __launch_bounds__(128, 2) k_attn(const float* __restrict__ kv_cache,
                                                 const int* __restrict__ kv_lens){
  extern __shared__ float kvs[];
  __shared__ float ps[4][32];
  int chunk = blockIdx.x, b = blockIdx.y;
  int len = kv_lens[b];
  int s_begin = chunk*CHUNK;
  if (s_begin > len) return;
  int s_end = min(s_begin + CHUNK, len + 1);
  int T = (s_end - s_begin + ATILE - 1)/ATILE;

  int tid = threadIdx.x;
  int warp = tid >> 5, lane = tid & 31;
  int myh = lane >> 3, myr = lane & 7;

  ulonglong2 q4[4][4]; ull qt[4];
  #pragma unroll
  for (int h = 0; h < 4; h++){
    const float* qf = g_qf + (size_t)(b*H + warp*4 + h)*DKV;
    #pragma unroll
    for (int j = 0; j < 4; j++) q4[h][j] = ((const ulonglong2*)qf)[j*32 + lane];
    qt[h] = ((const ull*)qf)[256 + lane];
  }

  ull acc[4][8];
  #pragma unroll
  for (int h = 0; h < 4; h++)
    #pragma unroll
    for (int j = 0; j < 8; j++) acc[h][j] = 0ull;
  float mh = -1e30f, lh = 0.f;

  auto load_tile = [&](int t){
    int buf = t & (NBUF-1);
    int t0 = s_begin + t*ATILE;
    int rows = min(ATILE, s_end - t0);
    float* dst = kvs + buf*(ATILE*DKV);
    for (int idx = tid; idx < rows*144; idx += 128){
      int r = idx/144, c4 = idx - r*144;
      int s = t0 + r;
      const float* src = (s == len) ? (g_newkv + b*DKV + c4*4)
                                    : (kv_cache + ((size_t)b*S + s)*DKV + c4*4);
      unsigned sa = (unsigned)__cvta_generic_to_shared(dst + r*DKV + c4*4);
      asm volatile("cp.async.cg.shared.global [%0], [%1], 16;" :: "r"(sa), "l"(src));
    }
    if (rows < ATILE)
      for (int idx = tid + rows*144; idx < ATILE*144; idx += 128){
        int r = idx/144, c4 = idx - r*144;
        *(float4*)(dst + r*DKV + c4*4) = make_float4(0.f,0.f,0.f,0.f);
      }
    asm volatile("cp.async.commit_group;" ::: "memory");
  };

  load_tile(0);
  if (T > 1) load_tile(1);
  if (T > 2) load_tile(2);
  for (int t = 0; t < T; t++){
    int rem = T - 1 - t;
    if (rem >= 2)      asm volatile("cp.async.wait_group 2;" ::: "memory");
    else if (rem == 1) asm volatile("cp.async.wait_group 1;" ::: "memory");
    else               asm volatile("cp.async.wait_group 0;" ::: "memory");
    __syncthreads();
    if (t + 3 < T) load_tile(t+3);

    const float* kb = kvs + (t & (NBUF-1))*(ATILE*DKV);
    int t0 = s_begin + t*ATILE;

    float x[32];
    #pragma unroll
    for (int r = 0; r < 8; r++){
      const ulonglong2* row4 = (const ulonglong2*)(kb + r*DKV);
      ull s0=0, s1=0, s2=0, s3=0;
      #pragma unroll
      for (int j = 0; j < 4; j++){
        ulonglong2 kv = row4[j*32 + lane];
        s0 = ffma2(q4[0][j].x, kv.x, s0); s0 = ffma2(q4[0][j].y, kv.y, s0);
        s1 = ffma2(q4[1][j].x, kv.x, s1); s1 = ffma2(q4[1][j].y, kv.y, s1);
        s2 = ffma2(q4[2][j].x, kv.x, s2); s2 = ffma2(q4[2][j].y, kv.y, s2);
        s3 = ffma2(q4[3][j].x, kv.x, s3); s3 = ffma2(q4[3][j].y, kv.y, s3);
      }
      ull kt = ((const ull*)(kb + r*DKV))[256 + lane];
      s0 = ffma2(qt[0], kt, s0);
      s1 = ffma2(qt[1], kt, s1);
      s2 = ffma2(qt[2], kt, s2);
      s3 = ffma2(qt[3], kt, s3);
      float2 v0=upk2(s0), v1=upk2(s1), v2=upk2(s2), v3=upk2(s3);
      x[0*8+r] = v0.x+v0.y; x[1*8+r] = v1.x+v1.y;
      x[2*8+r] = v2.x+v2.y; x[3*8+r] = v3.x+v3.y;
    }
    #pragma unroll
    for (int off = 16; off >= 1; off >>= 1){
      bool hi = (lane & off) != 0;
      #pragma unroll
      for (int i = 0; i < off; i++){
        float send = hi ? x[i] : x[i+off];
        float recv = __shfl_xor_sync(0xffffffffu, send, off);
        x[i] = (hi ? x[i+off] : x[i]) + recv;
      }
    }
    bool valid = (t0 + myr) < s_end;
    float sc = valid ? x[0] : -1e30f;

    float tm = sc;
    tm = fmaxf(tm, __shfl_xor_sync(0xffffffffu, tm, 4));
    tm = fmaxf(tm, __shfl_xor_sync(0xffffffffu, tm, 2));
    tm = fmaxf(tm, __shfl_xor_sync(0xffffffffu, tm, 1));
    float nm = fmaxf(mh, tm);
    float cf = __expf(mh - nm);
    mh = nm;
    float p = valid ? __expf(sc - nm) : 0.f;
    float sp = p;
    sp += __shfl_xor_sync(0xffffffffu, sp, 4);
    sp += __shfl_xor_sync(0xffffffffu, sp, 2);
    sp += __shfl_xor_sync(0xffffffffu, sp, 1);
    lh = lh*cf + sp;

    ps[warp][myr*4 + myh] = p;
    if (!__all_sync(0xffffffffu, cf == 1.0f)){
      #pragma unroll
      for (int h = 0; h < 4; h++){
        float cfh = __shfl_sync(0xffffffffu, cf, h*8);
        ull c2 = pk2(cfh, cfh);
        #pragma unroll
        for (int j = 0; j < 8; j++) acc[h][j] = fmul2(acc[h][j], c2);
      }
    }
    __syncwarp();

    #pragma unroll
    for (int r = 0; r < 8; r++){
      float4 pv = *(const float4*)&ps[warp][r*4];
      ull pp0 = pk2(pv.x,pv.x), pp1 = pk2(pv.y,pv.y), pp2 = pk2(pv.z,pv.z), pp3 = pk2(pv.w,pv.w);
      const ulonglong2* row4 = (const ulonglong2*)(kb + r*DKV);
      #pragma unroll
      for (int j = 0; j < 4; j++){
        ulonglong2 kv = row4[j*32 + lane];
        acc[0][2*j]   = ffma2(pp0, kv.x, acc[0][2*j]);
        acc[0][2*j+1] = ffma2(pp0, kv.y, acc[0][2*j+1]);
        acc[1][2*j]   = ffma2(pp1, kv.x, acc[1][2*j]);
        acc[1][2*j+1] = ffma2(pp1, kv.y, acc[1][2*j+1]);
        acc[2][2*j]   = ffma2(pp2, kv.x, acc[2][2*j]);
        acc[2][2*j+1] = ffma2(pp2, kv.y, acc[2][2*j+1]);
        acc[3][2*j]   = ffma2(pp3, kv.x, acc[3][2*j]);
        acc[3][2*j+1] = ffma2(pp3, kv.y, acc[3][2*j+1]);
      }
    }
  }

  #pragma unroll
  for (int h = 0; h < 4; h++){
    int basep = (b*H + warp*4 + h)*NCHUNK + chunk;
    if (lane == h*8){ g_m[basep] = mh; g_l[basep] = lh; }
    ull* op = (ull*)g_opart + (size_t)basep*256;
    #pragma unroll
    for (int j = 0; j < 4; j++){
      op[j*64 + lane*2]     = acc[h][2*j];
      op[j*64 + lane*2 + 1] = acc[h][2*j+1];
    }
  }
}

// ---------------- combine split-softmax partials (weights hoisted) ----------------
__global__ void __launch_bounds__(128) k_comb(const int* __restrict__ kv_lens){
  int h = blockIdx.x, b = blockIdx.y;
  int tid = threadIdx.x;
  int len = kv_lens[b];
  int cmax = min(NCHUNK - 1, len >> 8);
  int base = (b*H + h)*NCHUNK;
  float mstar = -1e30f;
  for (int c = 0; c <= cmax; c++) mstar = fmaxf(mstar, g_m[base + c]);
  float ecf[NCHUNK];
  float lstar = 0.f;
  for (int c = 0; c <= cmax; c++){
    float e = expf(g_m[base + c] - mstar);
    ecf[c] = e;
    lstar += e * g_l[base + c];
  }
  float inv_l = 1.f / lstar;
  #pragma unroll
  for (int j = 0; j < KV_LORA/128; j++){
    int d = tid + j*128;
    float s = 0.f;
    for (int c = 0; c <= cmax; c++)
      s += ecf[c] * g_opart[(size_t)(base + c)*KV_LORA + d];
    g_o[(size_t)(b*H + h)*KV_LORA + d] = s * inv_l;
  }
}

// ---------------- t = o @ W_Vd^T (fp8 weights) ----------------
__global__ void __launch_bounds__(256) k_v(){
  int cs = blockIdx.x, h = blockIdx.y;
  int tid = threadIdx.x;
  int vv = tid & 127, rg = tid >> 7;
  __shared__ float ws[128][33];
  __shared__ float os[B][32];
  float invV = g_wscale[1];
  float acc[16];
  #pragma unroll
  for (int i = 0; i < 16; i++) acc[i] = 0.f;
  for (int cbk = 0; cbk < 64; cbk += 32){
    int c0 = cs*64 + cbk;
    __syncthreads();
    #pragma unroll
    for (int it = 0; it < 4; it++){
      int idx = tid + it*256;
      int v = idx >> 3, d4 = (idx & 7)*4;
      const unsigned char* p = g_WV8 + (size_t)(h*VD + v)*KV_LORA + c0 + d4;
      uchar4 u = *(const uchar4*)p;
      ws[v][d4+0]=fp8tf(u.x); ws[v][d4+1]=fp8tf(u.y); ws[v][d4+2]=fp8tf(u.z); ws[v][d4+3]=fp8tf(u.w);
    }
    for (int idx = tid; idx < B*8; idx += 256){
      int r = idx >> 3, d4 = (idx & 7)*4;
      float4 v = *(const float4*)(g_o + (size_t)(r*H + h)*KV_LORA + c0 + d4);
      os[r][d4+0]=v.x; os[r][d4+1]=v.y; os[r][d4+2]=v.z; os[r][d4+3]=v.w;
    }
    __syncthreads();
    #pragma unroll
    for (int d = 0; d < 32; d++){
      float w = ws[vv][d];
      #pragma unroll
      for (int r = 0; r < 16; r++)
        acc[r] += os[rg*16 + r][d]*w;
    }
  }
  #pragma unroll
  for (int r = 0; r < 16; r++){
    int b = rg*16 + r;
    g_t_part[cs][b*HID + h*VD + vv] = acc[r]*invV;
  }
}

__global__ void k_tred(){
  int i = blockIdx.x*blockDim.x + threadIdx.x;
  if (i < B*HID){
    float s = 0.f;
    #pragma unroll
    for (int p = 0; p < VS; p++) s += g_t_part[p][i];
    g_t[i] = s;
  }
}

// ---------------- out = t @ Wo : KSO=16, 4 rows/thread, 128 cols/CTA (R12 shape) ----------------
__global__ void __launch_bounds__(256) k_out(const float* __restrict__ Wo){
  __shared__ float xs[B][128];
  __shared__ __align__(16) float ws[2][32][128];
  int cb = blockIdx.x, ks = blockIdx.y;
  int tid = threadIdx.x;
  int tx = tid & 31, ty = tid >> 5;
  int k0 = ks*128;
  #pragma unroll
  for (int it = 0; it < 4; it++){
    int idx = tid + it*256;
    int r = idx >> 5, c4 = idx & 31;
    float4 v = ((const float4*)g_t)[r*(HID/4) + (k0>>2) + c4];
    *(float4*)&xs[r][c4*4] = v;
  }
  auto loadw = [&](int c){
    int buf = c & 1;
    #pragma unroll
    for (int it = 0; it < 4; it++){
      int idx = tid + it*256;
      int r = idx >> 5, c4 = idx & 31;
      const float* src = Wo + (size_t)(k0 + c*32 + r)*HID + cb*128 + c4*4;
      unsigned sa = (unsigned)__cvta_generic_to_shared(&ws[buf][r][c4*4]);
      asm volatile("cp.async.cg.shared.global [%0], [%1], 16;" :: "r"(sa), "l"(src));
    }
    asm volatile("cp.async.commit_group;" ::: "memory");
  };
  loadw(0);
  ull acc[4][2] = {};
  for (int c = 0; c < 4; c++){
    if (c < 3){
      loadw(c+1);
      asm volatile("cp.async.wait_group 1;" ::: "memory");
    } else {
      asm volatile("cp.async.wait_group 0;" ::: "memory");
    }
    __syncthreads();
    int buf = c & 1;
    #pragma unroll
    for (int k = 0; k < 32; k++){
      ulonglong2 w2 = ((const ulonglong2*)&ws[buf][k][0])[tx];
      #pragma unroll
      for (int i = 0; i < 4; i++){
        float xv = xs[ty*4+i][c*32+k];
        ull xv2 = pk2(xv, xv);
        acc[i][0] = ffma2(xv2, w2.x, acc[i][0]);
        acc[i][1] = ffma2(xv2, w2.y, acc[i][1]);
      }
    }
    __syncthreads();
  }
  float4* op = (float4*)g_out_part[ks];
  #pragma unroll
  for (int i = 0; i < 4; i++){
    float2 a = upk2(acc[i][0]), b2 = upk2(acc[i][1]);
    op[(size_t)(ty*4+i)*(HID/4) + cb*32 + tx] = make_float4(a.x,a.y,b2.x,b2.y);
  }
}

__global__ void k_sum(float* __restrict__ out){
  int i = blockIdx.x*blockDim.x + threadIdx.x;
  if (i < B*HID){
    float s = 0.f;
    #pragma unroll
    for (int ks = 0; ks < KSO; ks++) s += g_out_part[ks][i];
    out[i] = s;
  }
}

extern "C" void kernel_launch(void* const* d_in, const int* in_sizes, int n_in,
                              void* d_out, int out_size){
  const float* q   = (const float*)d_in[0];
  const float* kc  = (const float*)d_in[1];
  const float* kpe = (const float*)d_in[2];
  const float* kvc = (const float*)d_in[3];
  const float* Wq  = (const float*)d_in[4];
  const float* WK  = (const float*)d_in[5];
  const float* WV  = (const float*)d_in[6];
  const float* Wo  = (const float*)d_in[7];
  const int*  lens = (const int*)d_in[8];

  cudaFuncSetAttribute(k_attn, cudaFuncAttributeMaxDynamicSharedMemorySize, NBUF*ATILE*DKV*4);

  k_rope<<<B, 32>>>(kpe, lens);
  k_amax<<<256, 256>>>(WK, WV);
  k_quant<<<512, 256>>>(WK, WV);
  k_qp<<<dim3(NQ/128, KSQ), 256>>>(q, Wq);
  k_qred<<<dim3(B, NQ/256), 256>>>(kc);
  k_qk<<<dim3(KV_LORA/64, H), 256>>>();
  k_attn<<<dim3(NCHUNK, B), 128, NBUF*ATILE*DKV*4>>>(kvc, lens);
  k_comb<<<dim3(H, B), 128>>>(lens);
  k_v<<<dim3(VS, H), 256>>>();
  k_tred<<<256, 256>>>();
  k_out<<<dim3(HID/128, KSO), 256>>>(Wo);
  k_sum<<<256, 256>>>((float*)d_out);
}

// round 15
// speedup vs baseline: 1.0539x; 1.0019x over previous
#include <cuda_runtime.h>
#include <cuda_fp8.h>
#include <math.h>

#define B 32
#define S 4096
#define H 16
#define KV_LORA 512
#define NOPE 128
#define ROPE 64
#define QKD 192
#define VD 128
#define QIN 1536
#define HID 2048
#define DKV 576
#define NQ (H*QKD)
#define SCALEF 0.07216878364870323f

#define CHUNK 256
#define NCHUNK (S/CHUNK)
#define ATILE 8
#define NBUF 4
#define KSQ 16
#define KSO 16
#define VS 8

typedef unsigned long long ull;

// ---------------- packed f32x2 helpers ----------------
__device__ __forceinline__ ull pk2(float x, float y){
  ull r; asm("mov.b64 %0, {%1, %2};" : "=l"(r) : "f"(x), "f"(y)); return r;
}
__device__ __forceinline__ float2 upk2(ull v){
  float2 r; asm("mov.b64 {%0, %1}, %2;" : "=f"(r.x), "=f"(r.y) : "l"(v)); return r;
}
__device__ __forceinline__ ull ffma2(ull a, ull b, ull c){
  ull d; asm("fma.rn.f32x2 %0, %1, %2, %3;" : "=l"(d) : "l"(a), "l"(b), "l"(c)); return d;
}
__device__ __forceinline__ ull fmul2(ull a, ull b){
  ull d; asm("mul.rn.f32x2 %0, %1, %2;" : "=l"(d) : "l"(a), "l"(b)); return d;
}

// ---------------- device scratch ----------------
static __device__ unsigned g_amax[2];
static __device__ float g_wscale[2];
static __device__ unsigned char g_WK8[H*KV_LORA*NOPE];
static __device__ unsigned char g_WV8[H*VD*KV_LORA];
static __device__ float g_qp_part[KSQ][B*NQ];
static __device__ float g_qn[B*H*NOPE];
static __device__ float g_qf[B*H*DKV];
static __device__ float g_newkv[B*DKV];
static __device__ float g_rope[B][32][2];
static __device__ float g_m[B*H*NCHUNK];
static __device__ float g_l[B*H*NCHUNK];
static __device__ float g_opart[(size_t)B*H*NCHUNK*KV_LORA];
static __device__ float g_o[B*H*KV_LORA];
static __device__ float g_t_part[VS][B*HID];
static __device__ float g_t[B*HID];
static __device__ float g_out_part[KSO][B*HID];

__global__ void k_amax(const float* __restrict__ WK, const float* __restrict__ WV){
  const int N4 = (H*KV_LORA*NOPE)/4;
  const float4* WK4 = (const float4*)WK;
  const float4* WV4 = (const float4*)WV;
  float m0 = 0.f, m1 = 0.f;
  for (int i = blockIdx.x*blockDim.x + threadIdx.x; i < N4; i += gridDim.x*blockDim.x){
    float4 a = WK4[i], b = WV4[i];
    m0 = fmaxf(m0, fmaxf(fmaxf(fabsf(a.x),fabsf(a.y)), fmaxf(fabsf(a.z),fabsf(a.w))));
    m1 = fmaxf(m1, fmaxf(fmaxf(fabsf(b.x),fabsf(b.y)), fmaxf(fabsf(b.z),fabsf(b.w))));
  }
  #pragma unroll
  for (int off = 16; off; off >>= 1){
    m0 = fmaxf(m0, __shfl_xor_sync(0xffffffffu, m0, off));
    m1 = fmaxf(m1, __shfl_xor_sync(0xffffffffu, m1, off));
  }
  __shared__ float s0[8], s1[8];
  int w = threadIdx.x >> 5;
  if ((threadIdx.x & 31) == 0){ s0[w] = m0; s1[w] = m1; }
  __syncthreads();
  if (threadIdx.x == 0){
    #pragma unroll
    for (int i = 1; i < 8; i++){ m0 = fmaxf(m0, s0[i]); m1 = fmaxf(m1, s1[i]); }
    atomicMax(&g_amax[0], __float_as_uint(m0));
    atomicMax(&g_amax[1], __float_as_uint(m1));
  }
}

// ---------------- rope trig table + new_kv rope ----------------
__global__ void k_rope(const float* __restrict__ kpe, const int* __restrict__ kv_lens){
  int b = blockIdx.x, i = threadIdx.x;
  int pos = kv_lens[b];
  double inv = exp(-((2.0*i)/64.0) * 9.210340371976184);
  double ang = (double)pos * inv;
  float cs = (float)cos(ang), sn = (float)sin(ang);
  g_rope[b][i][0] = cs;
  g_rope[b][i][1] = sn;
  float k1 = kpe[b*ROPE + i], k2 = kpe[b*ROPE + 32 + i];
  g_newkv[b*DKV + KV_LORA + i]      = k1*cs - k2*sn;
  g_newkv[b*DKV + KV_LORA + 32 + i] = k2*cs + k1*sn;
}

__device__ __forceinline__ unsigned q8(float v, float s){
  float x = fminf(fmaxf(v*s, -448.f), 448.f);
  return (unsigned)__nv_cvt_float_to_fp8(x, __NV_SATFINITE, __NV_E4M3);
}
__device__ __forceinline__ float fp8tf(unsigned char b){
  __half_raw h = __nv_cvt_fp8_to_halfraw((__nv_fp8_storage_t)b, __NV_E4M3);
  return __half2float(*(__half*)&h);
}

__global__ void k_quant(const float* __restrict__ WK, const float* __restrict__ WV){
  const int N16 = (H*KV_LORA*NOPE)/16;
  float aK = fmaxf(__uint_as_float(g_amax[0]), 1e-10f);
  float aV = fmaxf(__uint_as_float(g_amax[1]), 1e-10f);
  float sK = 448.f / aK, sV = 448.f / aV;
  if (blockIdx.x == 0 && threadIdx.x == 0){ g_wscale[0] = 1.f/sK; g_wscale[1] = 1.f/sV; }
  const float4* WK4 = (const float4*)WK;
  const float4* WV4 = (const float4*)WV;
  uint4* OK = (uint4*)g_WK8;
  uint4* OV = (uint4*)g_WV8;
  for (int i = blockIdx.x*blockDim.x + threadIdx.x; i < N16; i += gridDim.x*blockDim.x){
    uint4 ok, ov;
    unsigned* po = &ok.x;
    unsigned* pv = &ov.x;
    #pragma unroll
    for (int j = 0; j < 4; j++){
      float4 a = WK4[i*4 + j];
      po[j] = q8(a.x,sK) | (q8(a.y,sK)<<8) | (q8(a.z,sK)<<16) | (q8(a.w,sK)<<24);
      float4 b = WV4[i*4 + j];
      pv[j] = q8(b.x,sV) | (q8(b.y,sV)<<8) | (q8(b.z,sV)<<16) | (q8(b.w,sV)<<24);
    }
    OK[i] = ok; OV[i] = ov;
  }
}

// ---------------- qp = q @ Wq : KSQ=16, 4 rows/thread, 128 cols/CTA (R12 shape) ----------------
__global__ void __launch_bounds__(256) k_qp(const float* __restrict__ q,
                                            const float* __restrict__ Wq){
  __shared__ float xs[B][96];
  __shared__ __align__(16) float ws[2][32][128];
  int cb = blockIdx.x, ks = blockIdx.y;
  int tid = threadIdx.x;
  int tx = tid & 31, ty = tid >> 5;
  int k0 = ks*96;
  #pragma unroll
  for (int it = 0; it < 3; it++){
    int idx = tid + it*256;
    int r = idx/24, c4 = idx - r*24;
    float4 v = ((const float4*)q)[r*(QIN/4) + (k0>>2) + c4];
    *(float4*)&xs[r][c4*4] = v;
  }
  auto loadw = [&](int c){
    int buf = c & 1;
    #pragma unroll
    for (int it = 0; it < 4; it++){
      int idx = tid + it*256;
      int r = idx >> 5, c4 = idx & 31;
      const float* src = Wq + (size_t)(k0 + c*32 + r)*NQ + cb*128 + c4*4;
      unsigned sa = (unsigned)__cvta_generic_to_shared(&ws[buf][r][c4*4]);
      asm volatile("cp.async.cg.shared.global [%0], [%1], 16;" :: "r"(sa), "l"(src));
    }
    asm volatile("cp.async.commit_group;" ::: "memory");
  };
  loadw(0);
  ull acc[4][2] = {};
  for (int c = 0; c < 3; c++){
    if (c < 2){
      loadw(c+1);
      asm volatile("cp.async.wait_group 1;" ::: "memory");
    } else {
      asm volatile("cp.async.wait_group 0;" ::: "memory");
    }
    __syncthreads();
    int buf = c & 1;
    #pragma unroll
    for (int k = 0; k < 32; k++){
      ulonglong2 w2 = ((const ulonglong2*)&ws[buf][k][0])[tx];
      #pragma unroll
      for (int i = 0; i < 4; i++){
        float xv = xs[ty*4+i][c*32+k];
        ull xv2 = pk2(xv, xv);
        acc[i][0] = ffma2(xv2, w2.x, acc[i][0]);
        acc[i][1] = ffma2(xv2, w2.y, acc[i][1]);
      }
    }
    __syncthreads();
  }
  float4* op = (float4*)g_qp_part[ks];
  #pragma unroll
  for (int i = 0; i < 4; i++){
    float2 a = upk2(acc[i][0]), b2 = upk2(acc[i][1]);
    op[(size_t)(ty*4+i)*(NQ/4) + cb*32 + tx] = make_float4(a.x,a.y,b2.x,b2.y);
  }
}

// ---------------- reduce qp partials + rope (table) + new_kv copy ----------------
__global__ void __launch_bounds__(256) k_qred(const float* __restrict__ kc){
  int b = blockIdx.x, cy = blockIdx.y;
  int tid = threadIdx.x;
  __shared__ float qs[256];
  int cbase = cy*256;
  int col = tid;
  {
    float s = 0.f;
    #pragma unroll
    for (int ks = 0; ks < KSQ; ks++) s += g_qp_part[ks][b*NQ + cbase + col];
    qs[col] = s;
  }
  __syncthreads();
  {
    int gc = cbase + col;
    int h = gc/192, off = gc - h*192;
    if (off < 128){
      g_qn[(b*H + h)*NOPE + off] = qs[col];
    } else if (off < 160){
      int i = off - 128;
      float cs = g_rope[b][i][0], sn = g_rope[b][i][1];
      float x1 = qs[col], x2 = qs[col+32];
      float* qf = g_qf + (size_t)(b*H + h)*DKV;
      qf[KV_LORA + i]      = (x1*cs - x2*sn)*SCALEF;
      qf[KV_LORA + 32 + i] = (x2*cs + x1*sn)*SCALEF;
    }
  }
  if (cy < 2){
    int c = cy*256 + tid;
    g_newkv[b*DKV + c] = kc[b*KV_LORA + c];
  }
}

// ---------------- ql_nope = q_nope @ W_Kd^T (fp8 weights) ----------------
__global__ void __launch_bounds__(256) k_qk(){
  int h = blockIdx.y, c0 = blockIdx.x*64;
  int tid = threadIdx.x;
  int cc = tid & 63, rg = tid >> 6;
  __shared__ float qn_s[B][NOPE];
  __shared__ float ws[64][33];
  float invK = g_wscale[0];
  for (int idx = tid; idx < B*(NOPE/4); idx += 256){
    int r = idx >> 5, d4 = idx & 31;
    float4 v = ((const float4*)(g_qn + (size_t)(r*H + h)*NOPE))[d4];
    qn_s[r][d4*4+0]=v.x; qn_s[r][d4*4+1]=v.y; qn_s[r][d4*4+2]=v.z; qn_s[r][d4*4+3]=v.w;
  }
  float acc[8];
  #pragma unroll
  for (int i = 0; i < 8; i++) acc[i] = 0.f;
  for (int db = 0; db < NOPE; db += 32){
    __syncthreads();
    #pragma unroll
    for (int it = 0; it < 2; it++){
      int idx = tid + it*256;
      int c = idx >> 3, d4 = (idx & 7)*4;
      const unsigned char* p = g_WK8 + (size_t)(h*KV_LORA + c0 + c)*NOPE + db + d4;
      uchar4 v = *(const uchar4*)p;
      ws[c][d4+0]=fp8tf(v.x); ws[c][d4+1]=fp8tf(v.y); ws[c][d4+2]=fp8tf(v.z); ws[c][d4+3]=fp8tf(v.w);
    }
    __syncthreads();
    #pragma unroll
    for (int d = 0; d < 32; d++){
      float w = ws[cc][d];
      #pragma unroll
      for (int r = 0; r < 8; r++)
        acc[r] += qn_s[rg*8 + r][db + d]*w;
    }
  }
  float sc = SCALEF*invK;
  #pragma unroll
  for (int r = 0; r < 8; r++){
    int b = rg*8 + r;
    g_qf[(size_t)(b*H + h)*DKV + c0 + cc] = acc[r]*sc;
  }
}

// ---------------- flash attention (unchanged, measured best) ----------------
__global__ void __launch_bounds__(128, 2) k_attn(const float* __restrict__ kv_cache,
                                                 const int* __restrict__ kv_lens){
  extern __shared__ float kvs[];
  __shared__ float ps[4][32];
  int chunk = blockIdx.x, b = blockIdx.y;
  int len = kv_lens[b];
  int s_begin = chunk*CHUNK;
  if (s_begin > len) return;
  int s_end = min(s_begin + CHUNK, len + 1);
  int T = (s_end - s_begin + ATILE - 1)/ATILE;

  int tid = threadIdx.x;
  int warp = tid >> 5, lane = tid & 31;
  int myh = lane >> 3, myr = lane & 7;

  ulonglong2 q4[4][4]; ull qt[4];
  #pragma unroll
  for (int h = 0; h < 4; h++){
    const float* qf = g_qf + (size_t)(b*H + warp*4 + h)*DKV;
    #pragma unroll
    for (int j = 0; j < 4; j++) q4[h][j] = ((const ulonglong2*)qf)[j*32 + lane];
    qt[h] = ((const ull*)qf)[256 + lane];
  }

  ull acc[4][8];
  #pragma unroll
  for (int h = 0; h < 4; h++)
    #pragma unroll
    for (int j = 0; j < 8; j++) acc[h][j] = 0ull;
  float mh = -1e30f, lh = 0.f;

  auto load_tile = [&](int t){
    int buf = t & (NBUF-1);
    int t0 = s_begin + t*ATILE;
    int rows = min(ATILE, s_end - t0);
    float* dst = kvs + buf*(ATILE*DKV);
    for (int idx = tid; idx < rows*144; idx += 128){
      int r = idx/144, c4 = idx - r*144;
      int s = t0 + r;
      const float* src = (s == len) ? (g_newkv + b*DKV + c4*4)
                                    : (kv_cache + ((size_t)b*S + s)*DKV + c4*4);
      unsigned sa = (unsigned)__cvta_generic_to_shared(dst + r*DKV + c4*4);
      asm volatile("cp.async.cg.shared.global [%0], [%1], 16;" :: "r"(sa), "l"(src));
    }
    if (rows < ATILE)
      for (int idx = tid + rows*144; idx < ATILE*144; idx += 128){
        int r = idx/144, c4 = idx - r*144;
        *(float4*)(dst + r*DKV + c4*4) = make_float4(0.f,0.f,0.f,0.f);
      }
    asm volatile("cp.async.commit_group;" ::: "memory");
  };

  load_tile(0);
  if (T > 1) load_tile(1);
  if (T > 2) load_tile(2);
  for (int t = 0; t < T; t++){
    int rem = T - 1 - t;
    if (rem >= 2)      asm volatile("cp.async.wait_group 2;" ::: "memory");
    else if (rem == 1) asm volatile("cp.async.wait_group 1;" ::: "memory");
    else               asm volatile("cp.async.wait_group 0;" ::: "memory");
    __syncthreads();
    if (t + 3 < T) load_tile(t+3);

    const float* kb = kvs + (t & (NBUF-1))*(ATILE*DKV);
    int t0 = s_begin + t*ATILE;

    float x[32];
    #pragma unroll
    for (int r = 0; r < 8; r++){
      const ulonglong2* row4 = (const ulonglong2*)(kb + r*DKV);
      ull s0=0, s1=0, s2=0, s3=0;
      #pragma unroll
      for (int j = 0; j < 4; j++){
        ulonglong2 kv = row4[j*32 + lane];
        s0 = ffma2(q4[0][j].x, kv.x, s0); s0 = ffma2(q4[0][j].y, kv.y, s0);
        s1 = ffma2(q4[1][j].x, kv.x, s1); s1 = ffma2(q4[1][j].y, kv.y, s1);
        s2 = ffma2(q4[2][j].x, kv.x, s2); s2 = ffma2(q4[2][j].y, kv.y, s2);
        s3 = ffma2(q4[3][j].x, kv.x, s3); s3 = ffma2(q4[3][j].y, kv.y, s3);
      }
      ull kt = ((const ull*)(kb + r*DKV))[256 + lane];
      s0 = ffma2(qt[0], kt, s0);
      s1 = ffma2(qt[1], kt, s1);
      s2 = ffma2(qt[2], kt, s2);
      s3 = ffma2(qt[3], kt, s3);
      float2 v0=upk2(s0), v1=upk2(s1), v2=upk2(s2), v3=upk2(s3);
      x[0*8+r] = v0.x+v0.y; x[1*8+r] = v1.x+v1.y;
      x[2*8+r] = v2.x+v2.y; x[3*8+r] = v3.x+v3.y;
    }
    #pragma unroll
    for (int off = 16; off >= 1; off >>= 1){
      bool hi = (lane & off) != 0;
      #pragma unroll
      for (int i = 0; i < off; i++){
        float send = hi ? x[i] : x[i+off];
        float recv = __shfl_xor_sync(0xffffffffu, send, off);
        x[i] = (hi ? x[i+off] : x[i]) + recv;
      }
    }
    bool valid = (t0 + myr) < s_end;
    float sc = valid ? x[0] : -1e30f;

    float tm = sc;
    tm = fmaxf(tm, __shfl_xor_sync(0xffffffffu, tm, 4));
    tm = fmaxf(tm, __shfl_xor_sync(0xffffffffu, tm, 2));
    tm = fmaxf(tm, __shfl_xor_sync(0xffffffffu, tm, 1));
    float nm = fmaxf(mh, tm);
    float cf = __expf(mh - nm);
    mh = nm;
    float p = valid ? __expf(sc - nm) : 0.f;
    float sp = p;
    sp += __shfl_xor_sync(0xffffffffu, sp, 4);
    sp += __shfl_xor_sync(0xffffffffu, sp, 2);
    sp += __shfl_xor_sync(0xffffffffu, sp, 1);
    lh = lh*cf + sp;

    ps[warp][myr*4 + myh] = p;
    if (!__all_sync(0xffffffffu, cf == 1.0f)){
      #pragma unroll
      for (int h = 0; h < 4; h++){
        float cfh = __shfl_sync(0xffffffffu, cf, h*8);
        ull c2 = pk2(cfh, cfh);
        #pragma unroll
        for (int j = 0; j < 8; j++) acc[h][j] = fmul2(acc[h][j], c2);
      }
    }
    __syncwarp();

    #pragma unroll
    for (int r = 0; r < 8; r++){
      float4 pv = *(const float4*)&ps[warp][r*4];
      ull pp0 = pk2(pv.x,pv.x), pp1 = pk2(pv.y,pv.y), pp2 = pk2(pv.z,pv.z), pp3 = pk2(pv.w,pv.w);
      const ulonglong2* row4 = (const ulonglong2*)(kb + r*DKV);
      #pragma unroll
      for (int j = 0; j < 4; j++){
        ulonglong2 kv = row4[j*32 + lane];
        acc[0][2*j]   = ffma2(pp0, kv.x, acc[0][2*j]);
        acc[0][2*j+1] = ffma2(pp0, kv.y, acc[0][2*j+1]);
        acc[1][2*j]   = ffma2(pp1, kv.x, acc[1][2*j]);
        acc[1][2*j+1] = ffma2(pp1, kv.y, acc[1][2*j+1]);
        acc[2][2*j]   = ffma2(pp2, kv.x, acc[2][2*j]);
        acc[2][2*j+1] = ffma2(pp2, kv.y, acc[2][2*j+1]);
        acc[3][2*j]   = ffma2(pp3, kv.x, acc[3][2*j]);
        acc[3][2*j+1] = ffma2(pp3, kv.y, acc[3][2*j+1]);
      }
    }
  }

  #pragma unroll
  for (int h = 0; h < 4; h++){
    int basep = (b*H + warp*4 + h)*NCHUNK + chunk;
    if (lane == h*8){ g_m[basep] = mh; g_l[basep] = lh; }
    ull* op = (ull*)g_opart + (size_t)basep*256;
    #pragma unroll
    for (int j = 0; j < 4; j++){
      op[j*64 + lane*2]     = acc[h][2*j];
      op[j*64 + lane*2 + 1] = acc[h][2*j+1];
    }
  }
}

// ---------------- combine split-softmax partials (weights hoisted) ----------------
__global__ void __launch_bounds__(128) k_comb(const int* __restrict__ kv_lens){
  int h = blockIdx.x, b = blockIdx.y;
  int tid = threadIdx.x;
  int len = kv_lens[b];
  int cmax = min(NCHUNK - 1, len >> 8);
  int base = (b*H + h)*NCHUNK;
  float mstar = -1e30f;
  for (int c = 0; c <= cmax; c++) mstar = fmaxf(mstar, g_m[base + c]);
  float ecf[NCHUNK];
  float lstar = 0.f;
  for (int c = 0; c <= cmax; c++){
    float e = expf(g_m[base + c] - mstar);
    ecf[c] = e;
    lstar += e * g_l[base + c];
  }
  float inv_l = 1.f / lstar;
  #pragma unroll
  for (int j = 0; j < KV_LORA/128; j++){
    int d = tid + j*128;
    float s = 0.f;
    for (int c = 0; c <= cmax; c++)
      s += ecf[c] * g_opart[(size_t)(base + c)*KV_LORA + d];
    g_o[(size_t)(b*H + h)*KV_LORA + d] = s * inv_l;
  }
}

// ---------------- t = o @ W_Vd^T (fp8 weights) ----------------
__global__ void __launch_bounds__(256) k_v(){
  int cs = blockIdx.x, h = blockIdx.y;
  int tid = threadIdx.x;
  int vv = tid & 127, rg = tid >> 7;
  __shared__ float ws[128][33];
  __shared__ float os[B][32];
  float invV = g_wscale[1];
  float acc[16];
  #pragma unroll
  for (int i = 0; i < 16; i++) acc[i] = 0.f;
  for (int cbk = 0; cbk < 64; cbk += 32){
    int c0 = cs*64 + cbk;
    __syncthreads();
    #pragma unroll
    for (int it = 0; it < 4; it++){
      int idx = tid + it*256;
      int v = idx >> 3, d4 = (idx & 7)*4;
      const unsigned char* p = g_WV8 + (size_t)(h*VD + v)*KV_LORA + c0 + d4;
      uchar4 u = *(const uchar4*)p;
      ws[v][d4+0]=fp8tf(u.x); ws[v][d4+1]=fp8tf(u.y); ws[v][d4+2]=fp8tf(u.z); ws[v][d4+3]=fp8tf(u.w);
    }
    for (int idx = tid; idx < B*8; idx += 256){
      int r = idx >> 3, d4 = (idx & 7)*4;
      float4 v = *(const float4*)(g_o + (size_t)(r*H + h)*KV_LORA + c0 + d4);
      os[r][d4+0]=v.x; os[r][d4+1]=v.y; os[r][d4+2]=v.z; os[r][d4+3]=v.w;
    }
    __syncthreads();
    #pragma unroll
    for (int d = 0; d < 32; d++){
      float w = ws[vv][d];
      #pragma unroll
      for (int r = 0; r < 16; r++)
        acc[r] += os[rg*16 + r][d]*w;
    }
  }
  #pragma unroll
  for (int r = 0; r < 16; r++){
    int b = rg*16 + r;
    g_t_part[cs][b*HID + h*VD + vv] = acc[r]*invV;
  }
}

__global__ void k_tred(){
  int i = blockIdx.x*blockDim.x + threadIdx.x;
  if (i < B*HID){
    float s = 0.f;
    #pragma unroll
    for (int p = 0; p < VS; p++) s += g_t_part[p][i];
    g_t[i] = s;
  }
}

// ---------------- out = t @ Wo : KSO=16, 4 rows/thread, 128 cols/CTA (R12 shape) ----------------
__global__ void __launch_bounds__(256) k_out(const float* __restrict__ Wo){
  __shared__ float xs[B][128];
  __shared__ __align__(16) float ws[2][32][128];
  int cb = blockIdx.x, ks = blockIdx.y;
  int tid = threadIdx.x;
  int tx = tid & 31, ty = tid >> 5;
  int k0 = ks*128;
  #pragma unroll
  for (int it = 0; it < 4; it++){
    int idx = tid + it*256;
    int r = idx >> 5, c4 = idx & 31;
    float4 v = ((const float4*)g_t)[r*(HID/4) + (k0>>2) + c4];
    *(float4*)&xs[r][c4*4] = v;
  }
  auto loadw = [&](int c){
    int buf = c & 1;
    #pragma unroll
    for (int it = 0; it < 4; it++){
      int idx = tid + it*256;
      int r = idx >> 5, c4 = idx & 31;
      const float* src = Wo + (size_t)(k0 + c*32 + r)*HID + cb*128 + c4*4;
      unsigned sa = (unsigned)__cvta_generic_to_shared(&ws[buf][r][c4*4]);
      asm volatile("cp.async.cg.shared.global [%0], [%1], 16;" :: "r"(sa), "l"(src));
    }
    asm volatile("cp.async.commit_group;" ::: "memory");
  };
  loadw(0);
  ull acc[4][2] = {};
  for (int c = 0; c < 4; c++){
    if (c < 3){
      loadw(c+1);
      asm volatile("cp.async.wait_group 1;" ::: "memory");
    } else {
      asm volatile("cp.async.wait_group 0;" ::: "memory");
    }
    __syncthreads();
    int buf = c & 1;
    #pragma unroll
    for (int k = 0; k < 32; k++){
      ulonglong2 w2 = ((const ulonglong2*)&ws[buf][k][0])[tx];
      #pragma unroll
      for (int i = 0; i < 4; i++){
        float xv = xs[ty*4+i][c*32+k];
        ull xv2 = pk2(xv, xv);
        acc[i][0] = ffma2(xv2, w2.x, acc[i][0]);
        acc[i][1] = ffma2(xv2, w2.y, acc[i][1]);
      }
    }
    __syncthreads();
  }
  float4* op = (float4*)g_out_part[ks];
  #pragma unroll
  for (int i = 0; i < 4; i++){
    float2 a = upk2(acc[i][0]), b2 = upk2(acc[i][1]);
    op[(size_t)(ty*4+i)*(HID/4) + cb*32 + tx] = make_float4(a.x,a.y,b2.x,b2.y);
  }
}

__global__ void k_sum(float* __restrict__ out){
  int i = blockIdx.x*blockDim.x + threadIdx.x;
  if (i < B*HID){
    float s = 0.f;
    #pragma unroll
    for (int ks = 0; ks < KSO; ks++) s += g_out_part[ks][i];
    out[i] = s;
  }
}

extern "C" void kernel_launch(void* const* d_in, const int* in_sizes, int n_in,
                              void* d_out, int out_size){
  const float* q   = (const float*)d_in[0];
  const float* kc  = (const float*)d_in[1];
  const float* kpe = (const float*)d_in[2];
  const float* kvc = (const float*)d_in[3];
  const float* Wq  = (const float*)d_in[4];
  const float* WK  = (const float*)d_in[5];
  const float* WV  = (const float*)d_in[6];
  const float* Wo  = (const float*)d_in[7];
  const int*  lens = (const int*)d_in[8];

  // one-time host objects (created on the uncaptured correctness call)
  static cudaStream_t s1 = nullptr;
  static cudaEvent_t evFork = nullptr, evQuant = nullptr;
  if (!s1){
    cudaStreamCreateWithFlags(&s1, cudaStreamNonBlocking);
    cudaEventCreateWithFlags(&evFork, cudaEventDisableTiming);
    cudaEventCreateWithFlags(&evQuant, cudaEventDisableTiming);
    cudaFuncSetAttribute(k_attn, cudaFuncAttributeMaxDynamicSharedMemorySize, NBUF*ATILE*DKV*4);
  }

  // fork: weight quant path runs concurrently with q-projection path
  cudaEventRecord(evFork, 0);
  cudaStreamWaitEvent(s1, evFork, 0);
  k_amax<<<256, 256, 0, s1>>>(WK, WV);
  k_quant<<<512, 256, 0, s1>>>(WK, WV);
  cudaEventRecord(evQuant, s1);

  // main path
  k_rope<<<B, 32>>>(kpe, lens);
  k_qp<<<dim3(NQ/128, KSQ), 256>>>(q, Wq);
  k_qred<<<dim3(B, NQ/256), 256>>>(kc);

  // join: qk needs quantized WK8 + wscale
  cudaStreamWaitEvent(0, evQuant, 0);
  k_qk<<<dim3(KV_LORA/64, H), 256>>>();
  k_attn<<<dim3(NCHUNK, B), 128, NBUF*ATILE*DKV*4>>>(kvc, lens);
  k_comb<<<dim3(H, B), 128>>>(lens);
  k_v<<<dim3(VS, H), 256>>>();
  k_tred<<<256, 256>>>();
  k_out<<<dim3(HID/128, KSO), 256>>>(Wo);
  k_sum<<<256, 256>>>((float*)d_out);
}

// round 16
// speedup vs baseline: 1.0814x; 1.0261x over previous
#include <cuda_runtime.h>
#include <cuda_fp8.h>
#include <math.h>

#define B 32
#define S 4096
#define H 16
#define KV_LORA 512
#define NOPE 128
#define ROPE 64
#define QKD 192
#define VD 128
#define QIN 1536
#define HID 2048
#define DKV 576
#define NQ (H*QKD)
#define SCALEF 0.07216878364870323f

#define CHUNK 256
#define NCHUNK (S/CHUNK)
#define ATILE 8
#define NBUF 4
#define KSQ 16
#define KSO 16
#define VS 8

typedef unsigned long long ull;

// ---------------- packed f32x2 helpers ----------------
__device__ __forceinline__ ull pk2(float x, float y){
  ull r; asm("mov.b64 %0, {%1, %2};" : "=l"(r) : "f"(x), "f"(y)); return r;
}
__device__ __forceinline__ float2 upk2(ull v){
  float2 r; asm("mov.b64 {%0, %1}, %2;" : "=f"(r.x), "=f"(r.y) : "l"(v)); return r;
}
__device__ __forceinline__ ull ffma2(ull a, ull b, ull c){
  ull d; asm("fma.rn.f32x2 %0, %1, %2, %3;" : "=l"(d) : "l"(a), "l"(b), "l"(c)); return d;
}
__device__ __forceinline__ ull fmul2(ull a, ull b){
  ull d; asm("mul.rn.f32x2 %0, %1, %2;" : "=l"(d) : "l"(a), "l"(b)); return d;
}

// ---------------- device scratch ----------------
static __device__ unsigned g_amax[2];
static __device__ float g_wscale[2];
static __device__ unsigned char g_WK8[H*KV_LORA*NOPE];
static __device__ unsigned char g_WV8[H*VD*KV_LORA];
static __device__ float g_qp_part[KSQ][B*NQ];
static __device__ float g_qn[B*H*NOPE];
static __device__ float g_qf[B*H*DKV];
static __device__ float g_newkv[B*DKV];
static __device__ float g_rope[B][32][2];
static __device__ float g_m[B*H*NCHUNK];
static __device__ float g_l[B*H*NCHUNK];
static __device__ float g_opart[(size_t)B*H*NCHUNK*KV_LORA];
static __device__ float g_o[B*H*KV_LORA];
static __device__ float g_t_part[VS][B*HID];
static __device__ float g_t[B*HID];
static __device__ float g_out_part[KSO][B*HID];

__global__ void k_amax(const float* __restrict__ WK, const float* __restrict__ WV){
  const int N4 = (H*KV_LORA*NOPE)/4;
  const float4* WK4 = (const float4*)WK;
  const float4* WV4 = (const float4*)WV;
  float m0 = 0.f, m1 = 0.f;
  for (int i = blockIdx.x*blockDim.x + threadIdx.x; i < N4; i += gridDim.x*blockDim.x){
    float4 a = WK4[i], b = WV4[i];
    m0 = fmaxf(m0, fmaxf(fmaxf(fabsf(a.x),fabsf(a.y)), fmaxf(fabsf(a.z),fabsf(a.w))));
    m1 = fmaxf(m1, fmaxf(fmaxf(fabsf(b.x),fabsf(b.y)), fmaxf(fabsf(b.z),fabsf(b.w))));
  }
  #pragma unroll
  for (int off = 16; off; off >>= 1){
    m0 = fmaxf(m0, __shfl_xor_sync(0xffffffffu, m0, off));
    m1 = fmaxf(m1, __shfl_xor_sync(0xffffffffu, m1, off));
  }
  __shared__ float s0[8], s1[8];
  int w = threadIdx.x >> 5;
  if ((threadIdx.x & 31) == 0){ s0[w] = m0; s1[w] = m1; }
  __syncthreads();
  if (threadIdx.x == 0){
    #pragma unroll
    for (int i = 1; i < 8; i++){ m0 = fmaxf(m0, s0[i]); m1 = fmaxf(m1, s1[i]); }
    atomicMax(&g_amax[0], __float_as_uint(m0));
    atomicMax(&g_amax[1], __float_as_uint(m1));
  }
}

// ---------------- rope trig table + new_kv rope ----------------
__global__ void k_rope(const float* __restrict__ kpe, const int* __restrict__ kv_lens){
  int b = blockIdx.x, i = threadIdx.x;
  int pos = kv_lens[b];
  double inv = exp(-((2.0*i)/64.0) * 9.210340371976184);
  double ang = (double)pos * inv;
  float cs = (float)cos(ang), sn = (float)sin(ang);
  g_rope[b][i][0] = cs;
  g_rope[b][i][1] = sn;
  float k1 = kpe[b*ROPE + i], k2 = kpe[b*ROPE + 32 + i];
  g_newkv[b*DKV + KV_LORA + i]      = k1*cs - k2*sn;
  g_newkv[b*DKV + KV_LORA + 32 + i] = k2*cs + k1*sn;
}

__device__ __forceinline__ unsigned q8(float v, float s){
  float x = fminf(fmaxf(v*s, -448.f), 448.f);
  return (unsigned)__nv_cvt_float_to_fp8(x, __NV_SATFINITE, __NV_E4M3);
}
__device__ __forceinline__ float fp8tf(unsigned char b){
  __half_raw h = __nv_cvt_fp8_to_halfraw((__nv_fp8_storage_t)b, __NV_E4M3);
  return __half2float(*(__half*)&h);
}

__global__ void k_quant(const float* __restrict__ WK, const float* __restrict__ WV){
  const int N16 = (H*KV_LORA*NOPE)/16;
  float aK = fmaxf(__uint_as_float(g_amax[0]), 1e-10f);
  float aV = fmaxf(__uint_as_float(g_amax[1]), 1e-10f);
  float sK = 448.f / aK, sV = 448.f / aV;
  if (blockIdx.x == 0 && threadIdx.x == 0){ g_wscale[0] = 1.f/sK; g_wscale[1] = 1.f/sV; }
  const float4* WK4 = (const float4*)WK;
  const float4* WV4 = (const float4*)WV;
  uint4* OK = (uint4*)g_WK8;
  uint4* OV = (uint4*)g_WV8;
  for (int i = blockIdx.x*blockDim.x + threadIdx.x; i < N16; i += gridDim.x*blockDim.x){
    uint4 ok, ov;
    unsigned* po = &ok.x;
    unsigned* pv = &ov.x;
    #pragma unroll
    for (int j = 0; j < 4; j++){
      float4 a = WK4[i*4 + j];
      po[j] = q8(a.x,sK) | (q8(a.y,sK)<<8) | (q8(a.z,sK)<<16) | (q8(a.w,sK)<<24);
      float4 b = WV4[i*4 + j];
      pv[j] = q8(b.x,sV) | (q8(b.y,sV)<<8) | (q8(b.z,sV)<<16) | (q8(b.w,sV)<<24);
    }
    OK[i] = ok; OV[i] = ov;
  }
}

// ---------------- qp = q @ Wq : KSQ=16, 4 rows/thread, 128 cols/CTA ----------------
__global__ void __launch_bounds__(256) k_qp(const float* __restrict__ q,
                                            const float* __restrict__ Wq){
  __shared__ float xs[B][96];
  __shared__ __align__(16) float ws[2][32][128];
  int cb = blockIdx.x, ks = blockIdx.y;
  int tid = threadIdx.x;
  int tx = tid & 31, ty = tid >> 5;
  int k0 = ks*96;
  #pragma unroll
  for (int it = 0; it < 3; it++){
    int idx = tid + it*256;
    int r = idx/24, c4 = idx - r*24;
    float4 v = ((const float4*)q)[r*(QIN/4) + (k0>>2) + c4];
    *(float4*)&xs[r][c4*4] = v;
  }
  auto loadw = [&](int c){
    int buf = c & 1;
    #pragma unroll
    for (int it = 0; it < 4; it++){
      int idx = tid + it*256;
      int r = idx >> 5, c4 = idx & 31;
      const float* src = Wq + (size_t)(k0 + c*32 + r)*NQ + cb*128 + c4*4;
      unsigned sa = (unsigned)__cvta_generic_to_shared(&ws[buf][r][c4*4]);
      asm volatile("cp.async.cg.shared.global [%0], [%1], 16;" :: "r"(sa), "l"(src));
    }
    asm volatile("cp.async.commit_group;" ::: "memory");
  };
  loadw(0);
  ull acc[4][2] = {};
  for (int c = 0; c < 3; c++){
    if (c < 2){
      loadw(c+1);
      asm volatile("cp.async.wait_group 1;" ::: "memory");
    } else {
      asm volatile("cp.async.wait_group 0;" ::: "memory");
    }
    __syncthreads();
    int buf = c & 1;
    #pragma unroll
    for (int k = 0; k < 32; k++){
      ulonglong2 w2 = ((const ulonglong2*)&ws[buf][k][0])[tx];
      #pragma unroll
      for (int i = 0; i < 4; i++){
        float xv = xs[ty*4+i][c*32+k];
        ull xv2 = pk2(xv, xv);
        acc[i][0] = ffma2(xv2, w2.x, acc[i][0]);
        acc[i][1] = ffma2(xv2, w2.y, acc[i][1]);
      }
    }
    __syncthreads();
  }
  float4* op = (float4*)g_qp_part[ks];
  #pragma unroll
  for (int i = 0; i < 4; i++){
    float2 a = upk2(acc[i][0]), b2 = upk2(acc[i][1]);
    op[(size_t)(ty*4+i)*(NQ/4) + cb*32 + tx] = make_float4(a.x,a.y,b2.x,b2.y);
  }
}

// ---------------- reduce qp partials + rope (table) + new_kv copy ----------------
__global__ void __launch_bounds__(256) k_qred(const float* __restrict__ kc){
  int b = blockIdx.x, cy = blockIdx.y;
  int tid = threadIdx.x;
  __shared__ float qs[256];
  int cbase = cy*256;
  int col = tid;
  {
    float s = 0.f;
    #pragma unroll
    for (int ks = 0; ks < KSQ; ks++) s += g_qp_part[ks][b*NQ + cbase + col];
    qs[col] = s;
  }
  __syncthreads();
  {
    int gc = cbase + col;
    int h = gc/192, off = gc - h*192;
    if (off < 128){
      g_qn[(b*H + h)*NOPE + off] = qs[col];
    } else if (off < 160){
      int i = off - 128;
      float cs = g_rope[b][i][0], sn = g_rope[b][i][1];
      float x1 = qs[col], x2 = qs[col+32];
      float* qf = g_qf + (size_t)(b*H + h)*DKV;
      qf[KV_LORA + i]      = (x1*cs - x2*sn)*SCALEF;
      qf[KV_LORA + 32 + i] = (x2*cs + x1*sn)*SCALEF;
    }
  }
  if (cy < 2){
    int c = cy*256 + tid;
    g_newkv[b*DKV + c] = kc[b*KV_LORA + c];
  }
}

// ---------------- ql_nope = q_nope @ W_Kd^T (fp8 weights) ----------------
__global__ void __launch_bounds__(256) k_qk(){
  int h = blockIdx.y, c0 = blockIdx.x*64;
  int tid = threadIdx.x;
  int cc = tid & 63, rg = tid >> 6;
  __shared__ float qn_s[B][NOPE];
  __shared__ float ws[64][33];
  float invK = g_wscale[0];
  for (int idx = tid; idx < B*(NOPE/4); idx += 256){
    int r = idx >> 5, d4 = idx & 31;
    float4 v = ((const float4*)(g_qn + (size_t)(r*H + h)*NOPE))[d4];
    qn_s[r][d4*4+0]=v.x; qn_s[r][d4*4+1]=v.y; qn_s[r][d4*4+2]=v.z; qn_s[r][d4*4+3]=v.w;
  }
  float acc[8];
  #pragma unroll
  for (int i = 0; i < 8; i++) acc[i] = 0.f;
  for (int db = 0; db < NOPE; db += 32){
    __syncthreads();
    #pragma unroll
    for (int it = 0; it < 2; it++){
      int idx = tid + it*256;
      int c = idx >> 3, d4 = (idx & 7)*4;
      const unsigned char* p = g_WK8 + (size_t)(h*KV_LORA + c0 + c)*NOPE + db + d4;
      uchar4 v = *(const uchar4*)p;
      ws[c][d4+0]=fp8tf(v.x); ws[c][d4+1]=fp8tf(v.y); ws[c][d4+2]=fp8tf(v.z); ws[c][d4+3]=fp8tf(v.w);
    }
    __syncthreads();
    #pragma unroll
    for (int d = 0; d < 32; d++){
      float w = ws[cc][d];
      #pragma unroll
      for (int r = 0; r < 8; r++)
        acc[r] += qn_s[rg*8 + r][db + d]*w;
    }
  }
  float sc = SCALEF*invK;
  #pragma unroll
  for (int r = 0; r < 8; r++){
    int b = rg*8 + r;
    g_qf[(size_t)(b*H + h)*DKV + c0 + cc] = acc[r]*sc;
  }
}

// ---------------- flash attention: 2 tiles per softmax epoch ----------------
__global__ void __launch_bounds__(128, 2) k_attn(const float* __restrict__ kv_cache,
                                                 const int* __restrict__ kv_lens){
  extern __shared__ float kvs[];
  __shared__ float ps[4][64];
  int chunk = blockIdx.x, b = blockIdx.y;
  int len = kv_lens[b];
  int s_begin = chunk*CHUNK;
  if (s_begin > len) return;
  int s_end = min(s_begin + CHUNK, len + 1);
  int T = (s_end - s_begin + ATILE - 1)/ATILE;
  int E = (T + 1) >> 1;

  int tid = threadIdx.x;
  int warp = tid >> 5, lane = tid & 31;
  int myh = lane >> 3, myr = lane & 7;

  ulonglong2 q4[4][4]; ull qt[4];
  #pragma unroll
  for (int h = 0; h < 4; h++){
    const float* qf = g_qf + (size_t)(b*H + warp*4 + h)*DKV;
    #pragma unroll
    for (int j = 0; j < 4; j++) q4[h][j] = ((const ulonglong2*)qf)[j*32 + lane];
    qt[h] = ((const ull*)qf)[256 + lane];
  }

  ull acc[4][8];
  #pragma unroll
  for (int h = 0; h < 4; h++)
    #pragma unroll
    for (int j = 0; j < 8; j++) acc[h][j] = 0ull;
  float mh = -1e30f, lh = 0.f;

  auto load_tile = [&](int t){
    int buf = t & (NBUF-1);
    int t0 = s_begin + t*ATILE;
    int rows = min(ATILE, s_end - t0);
    float* dst = kvs + buf*(ATILE*DKV);
    for (int idx = tid; idx < rows*144; idx += 128){
      int r = idx/144, c4 = idx - r*144;
      int s = t0 + r;
      const float* src = (s == len) ? (g_newkv + b*DKV + c4*4)
                                    : (kv_cache + ((size_t)b*S + s)*DKV + c4*4);
      unsigned sa = (unsigned)__cvta_generic_to_shared(dst + r*DKV + c4*4);
      asm volatile("cp.async.cg.shared.global [%0], [%1], 16;" :: "r"(sa), "l"(src));
    }
    if (rows < ATILE)
      for (int idx = tid + rows*144; idx < ATILE*144; idx += 128){
        int r = idx/144, c4 = idx - r*144;
        *(float4*)(dst + r*DKV + c4*4) = make_float4(0.f,0.f,0.f,0.f);
      }
    asm volatile("cp.async.commit_group;" ::: "memory");
  };

  // score fold helper: fills x[h*8+r] for 8 rows of kb, returns lane value
  auto score8 = [&](const float* kb, float* x){
    #pragma unroll
    for (int r = 0; r < 8; r++){
      const ulonglong2* row4 = (const ulonglong2*)(kb + r*DKV);
      ull s0=0, s1=0, s2=0, s3=0;
      #pragma unroll
      for (int j = 0; j < 4; j++){
        ulonglong2 kv = row4[j*32 + lane];
        s0 = ffma2(q4[0][j].x, kv.x, s0); s0 = ffma2(q4[0][j].y, kv.y, s0);
        s1 = ffma2(q4[1][j].x, kv.x, s1); s1 = ffma2(q4[1][j].y, kv.y, s1);
        s2 = ffma2(q4[2][j].x, kv.x, s2); s2 = ffma2(q4[2][j].y, kv.y, s2);
        s3 = ffma2(q4[3][j].x, kv.x, s3); s3 = ffma2(q4[3][j].y, kv.y, s3);
      }
      ull kt = ((const ull*)(kb + r*DKV))[256 + lane];
      s0 = ffma2(qt[0], kt, s0);
      s1 = ffma2(qt[1], kt, s1);
      s2 = ffma2(qt[2], kt, s2);
      s3 = ffma2(qt[3], kt, s3);
      float2 v0=upk2(s0), v1=upk2(s1), v2=upk2(s2), v3=upk2(s3);
      x[0*8+r] = v0.x+v0.y; x[1*8+r] = v1.x+v1.y;
      x[2*8+r] = v2.x+v2.y; x[3*8+r] = v3.x+v3.y;
    }
    #pragma unroll
    for (int off = 16; off >= 1; off >>= 1){
      bool hi = (lane & off) != 0;
      #pragma unroll
      for (int i = 0; i < off; i++){
        float send = hi ? x[i] : x[i+off];
        float recv = __shfl_xor_sync(0xffffffffu, send, off);
        x[i] = (hi ? x[i+off] : x[i]) + recv;
      }
    }
    return x[0];
  };

  load_tile(0);
  if (T > 1) load_tile(1);
  for (int e = 0; e < E; e++){
    int t0 = 2*e, t1 = 2*e + 1;
    __syncthreads();                         // frees bufs of epoch e-1
    if (t0 + 2 < T) load_tile(t0 + 2);
    if (t0 + 3 < T) load_tile(t0 + 3);
    {
      int issued = min(2*e + 4, T);
      int needed = min(t1 + 1, T);
      int pend = issued - needed;
      if (pend >= 2)      asm volatile("cp.async.wait_group 2;" ::: "memory");
      else if (pend == 1) asm volatile("cp.async.wait_group 1;" ::: "memory");
      else                asm volatile("cp.async.wait_group 0;" ::: "memory");
    }

    const float* kb1 = kvs + (t0 & (NBUF-1))*(ATILE*DKV);
    bool has2 = (t1 < T);
    const float* kb2 = has2 ? kvs + (t1 & (NBUF-1))*(ATILE*DKV) : kb1;
    int g0 = s_begin + e*16;

    float x[32];
    float sA = score8(kb1, x);
    float sB = score8(kb2, x);

    bool v1 = (g0 + myr) < s_end;
    bool v2 = (g0 + 8 + myr) < s_end;
    float s1 = v1 ? sA : -1e30f;
    float s2 = v2 ? sB : -1e30f;

    float tm = fmaxf(s1, s2);
    tm = fmaxf(tm, __shfl_xor_sync(0xffffffffu, tm, 4));
    tm = fmaxf(tm, __shfl_xor_sync(0xffffffffu, tm, 2));
    tm = fmaxf(tm, __shfl_xor_sync(0xffffffffu, tm, 1));
    float nm = fmaxf(mh, tm);
    float cf = __expf(mh - nm);
    mh = nm;
    float p1 = v1 ? __expf(s1 - nm) : 0.f;
    float p2 = v2 ? __expf(s2 - nm) : 0.f;
    float sp = p1 + p2;
    sp += __shfl_xor_sync(0xffffffffu, sp, 4);
    sp += __shfl_xor_sync(0xffffffffu, sp, 2);
    sp += __shfl_xor_sync(0xffffffffu, sp, 1);
    lh = lh*cf + sp;

    ps[warp][myr*4 + myh]      = p1;
    ps[warp][32 + myr*4 + myh] = p2;
    if (!__all_sync(0xffffffffu, cf == 1.0f)){
      #pragma unroll
      for (int h = 0; h < 4; h++){
        float cfh = __shfl_sync(0xffffffffu, cf, h*8);
        ull c2 = pk2(cfh, cfh);
        #pragma unroll
        for (int j = 0; j < 8; j++) acc[h][j] = fmul2(acc[h][j], c2);
      }
    }
    __syncwarp();

    #pragma unroll
    for (int half = 0; half < 2; half++){
      const float* kb = half ? kb2 : kb1;
      #pragma unroll
      for (int r = 0; r < 8; r++){
        float4 pv = *(const float4*)&ps[warp][half*32 + r*4];
        ull pp0 = pk2(pv.x,pv.x), pp1 = pk2(pv.y,pv.y), pp2 = pk2(pv.z,pv.z), pp3 = pk2(pv.w,pv.w);
        const ulonglong2* row4 = (const ulonglong2*)(kb + r*DKV);
        #pragma unroll
        for (int j = 0; j < 4; j++){
          ulonglong2 kv = row4[j*32 + lane];
          acc[0][2*j]   = ffma2(pp0, kv.x, acc[0][2*j]);
          acc[0][2*j+1] = ffma2(pp0, kv.y, acc[0][2*j+1]);
          acc[1][2*j]   = ffma2(pp1, kv.x, acc[1][2*j]);
          acc[1][2*j+1] = ffma2(pp1, kv.y, acc[1][2*j+1]);
          acc[2][2*j]   = ffma2(pp2, kv.x, acc[2][2*j]);
          acc[2][2*j+1] = ffma2(pp2, kv.y, acc[2][2*j+1]);
          acc[3][2*j]   = ffma2(pp3, kv.x, acc[3][2*j]);
          acc[3][2*j+1] = ffma2(pp3, kv.y, acc[3][2*j+1]);
        }
      }
    }
  }

  #pragma unroll
  for (int h = 0; h < 4; h++){
    int basep = (b*H + warp*4 + h)*NCHUNK + chunk;
    if (lane == h*8){ g_m[basep] = mh; g_l[basep] = lh; }
    ull* op = (ull*)g_opart + (size_t)basep*256;
    #pragma unroll
    for (int j = 0; j < 4; j++){
      op[j*64 + lane*2]     = acc[h][2*j];
      op[j*64 + lane*2 + 1] = acc[h][2*j+1];
    }
  }
}

// ---------------- combine split-softmax partials ----------------
__global__ void __launch_bounds__(128) k_comb(const int* __restrict__ kv_lens){
  int h = blockIdx.x, b = blockIdx.y;
  int tid = threadIdx.x;
  int len = kv_lens[b];
  int cmax = min(NCHUNK - 1, len >> 8);
  int base = (b*H + h)*NCHUNK;
  float mstar = -1e30f;
  for (int c = 0; c <= cmax; c++) mstar = fmaxf(mstar, g_m[base + c]);
  float ecf[NCHUNK];
  float lstar = 0.f;
  for (int c = 0; c <= cmax; c++){
    float e = expf(g_m[base + c] - mstar);
    ecf[c] = e;
    lstar += e * g_l[base + c];
  }
  float inv_l = 1.f / lstar;
  #pragma unroll
  for (int j = 0; j < KV_LORA/128; j++){
    int d = tid + j*128;
    float s = 0.f;
    for (int c = 0; c <= cmax; c++)
      s += ecf[c] * g_opart[(size_t)(base + c)*KV_LORA + d];
    g_o[(size_t)(b*H + h)*KV_LORA + d] = s * inv_l;
  }
}

// ---------------- t = o @ W_Vd^T (fp8 weights) ----------------
__global__ void __launch_bounds__(256) k_v(){
  int cs = blockIdx.x, h = blockIdx.y;
  int tid = threadIdx.x;
  int vv = tid & 127, rg = tid >> 7;
  __shared__ float ws[128][33];
  __shared__ float os[B][32];
  float invV = g_wscale[1];
  float acc[16];
  #pragma unroll
  for (int i = 0; i < 16; i++) acc[i] = 0.f;
  for (int cbk = 0; cbk < 64; cbk += 32){
    int c0 = cs*64 + cbk;
    __syncthreads();
    #pragma unroll
    for (int it = 0; it < 4; it++){
      int idx = tid + it*256;
      int v = idx >> 3, d4 = (idx & 7)*4;
      const unsigned char* p = g_WV8 + (size_t)(h*VD + v)*KV_LORA + c0 + d4;
      uchar4 u = *(const uchar4*)p;
      ws[v][d4+0]=fp8tf(u.x); ws[v][d4+1]=fp8tf(u.y); ws[v][d4+2]=fp8tf(u.z); ws[v][d4+3]=fp8tf(u.w);
    }
    for (int idx = tid; idx < B*8; idx += 256){
      int r = idx >> 3, d4 = (idx & 7)*4;
      float4 v = *(const float4*)(g_o + (size_t)(r*H + h)*KV_LORA + c0 + d4);
      os[r][d4+0]=v.x; os[r][d4+1]=v.y; os[r][d4+2]=v.z; os[r][d4+3]=v.w;
    }
    __syncthreads();
    #pragma unroll
    for (int d = 0; d < 32; d++){
      float w = ws[vv][d];
      #pragma unroll
      for (int r = 0; r < 16; r++)
        acc[r] += os[rg*16 + r][d]*w;
    }
  }
  #pragma unroll
  for (int r = 0; r < 16; r++){
    int b = rg*16 + r;
    g_t_part[cs][b*HID + h*VD + vv] = acc[r]*invV;
  }
}

__global__ void k_tred(){
  int i = blockIdx.x*blockDim.x + threadIdx.x;
  if (i < B*HID){
    float s = 0.f;
    #pragma unroll
    for (int p = 0; p < VS; p++) s += g_t_part[p][i];
    g_t[i] = s;
  }
}

// ---------------- out = t @ Wo : KSO=16, 4 rows/thread, 128 cols/CTA ----------------
__global__ void __launch_bounds__(256) k_out(const float* __restrict__ Wo){
  __shared__ float xs[B][128];
  __shared__ __align__(16) float ws[2][32][128];
  int cb = blockIdx.x, ks = blockIdx.y;
  int tid = threadIdx.x;
  int tx = tid & 31, ty = tid >> 5;
  int k0 = ks*128;
  #pragma unroll
  for (int it = 0; it < 4; it++){
    int idx = tid + it*256;
    int r = idx >> 5, c4 = idx & 31;
    float4 v = ((const float4*)g_t)[r*(HID/4) + (k0>>2) + c4];
    *(float4*)&xs[r][c4*4] = v;
  }
  auto loadw = [&](int c){
    int buf = c & 1;
    #pragma unroll
    for (int it = 0; it < 4; it++){
      int idx = tid + it*256;
      int r = idx >> 5, c4 = idx & 31;
      const float* src = Wo + (size_t)(k0 + c*32 + r)*HID + cb*128 + c4*4;
      unsigned sa = (unsigned)__cvta_generic_to_shared(&ws[buf][r][c4*4]);
      asm volatile("cp.async.cg.shared.global [%0], [%1], 16;" :: "r"(sa), "l"(src));
    }
    asm volatile("cp.async.commit_group;" ::: "memory");
  };
  loadw(0);
  ull acc[4][2] = {};
  for (int c = 0; c < 4; c++){
    if (c < 3){
      loadw(c+1);
      asm volatile("cp.async.wait_group 1;" ::: "memory");
    } else {
      asm volatile("cp.async.wait_group 0;" ::: "memory");
    }
    __syncthreads();
    int buf = c & 1;
    #pragma unroll
    for (int k = 0; k < 32; k++){
      ulonglong2 w2 = ((const ulonglong2*)&ws[buf][k][0])[tx];
      #pragma unroll
      for (int i = 0; i < 4; i++){
        float xv = xs[ty*4+i][c*32+k];
        ull xv2 = pk2(xv, xv);
        acc[i][0] = ffma2(xv2, w2.x, acc[i][0]);
        acc[i][1] = ffma2(xv2, w2.y, acc[i][1]);
      }
    }
    __syncthreads();
  }
  float4* op = (float4*)g_out_part[ks];
  #pragma unroll
  for (int i = 0; i < 4; i++){
    float2 a = upk2(acc[i][0]), b2 = upk2(acc[i][1]);
    op[(size_t)(ty*4+i)*(HID/4) + cb*32 + tx] = make_float4(a.x,a.y,b2.x,b2.y);
  }
}

__global__ void k_sum(float* __restrict__ out){
  int i = blockIdx.x*blockDim.x + threadIdx.x;
  if (i < B*HID){
    float s = 0.f;
    #pragma unroll
    for (int ks = 0; ks < KSO; ks++) s += g_out_part[ks][i];
    out[i] = s;
  }
}

extern "C" void kernel_launch(void* const* d_in, const int* in_sizes, int n_in,
                              void* d_out, int out_size){
  const float* q   = (const float*)d_in[0];
  const float* kc  = (const float*)d_in[1];
  const float* kpe = (const float*)d_in[2];
  const float* kvc = (const float*)d_in[3];
  const float* Wq  = (const float*)d_in[4];
  const float* WK  = (const float*)d_in[5];
  const float* WV  = (const float*)d_in[6];
  const float* Wo  = (const float*)d_in[7];
  const int*  lens = (const int*)d_in[8];

  cudaFuncSetAttribute(k_attn, cudaFuncAttributeMaxDynamicSharedMemorySize, NBUF*ATILE*DKV*4);

  k_rope<<<B, 32>>>(kpe, lens);
  k_amax<<<256, 256>>>(WK, WV);
  k_quant<<<512, 256>>>(WK, WV);
  k_qp<<<dim3(NQ/128, KSQ), 256>>>(q, Wq);
  k_qred<<<dim3(B, NQ/256), 256>>>(kc);
  k_qk<<<dim3(KV_LORA/64, H), 256>>>();
  k_attn<<<dim3(NCHUNK, B), 128, NBUF*ATILE*DKV*4>>>(kvc, lens);
  k_comb<<<dim3(H, B), 128>>>(lens);
  k_v<<<dim3(VS, H), 256>>>();
  k_tred<<<256, 256>>>();
  k_out<<<dim3(HID/128, KSO), 256>>>(Wo);
  k_sum<<<256, 256>>>((float*)d_out);
}